// round 1
// baseline (speedup 1.0000x reference)
#include <cuda_runtime.h>
#include <math.h>

#define NN 100000
#define NE 1600000

// ---------------- scratch (static device globals; no runtime allocation) ----
__device__ float g_H0  [(size_t)NN*256];
__device__ float g_H1  [(size_t)NN*128];
__device__ float g_HW1 [(size_t)NN*64];   // hw1*dinv (then reused as conv1 activated output)
__device__ float g_AGG1[(size_t)NN*64];
__device__ float g_GI1 [(size_t)NN*192];
__device__ float g_GH1 [(size_t)NN*192];
__device__ float g_HW2 [(size_t)NN*32];   // hw2*dinv (then reused as conv2 activated output)
__device__ float g_AGG2[(size_t)NN*32];
__device__ float g_GI2 [(size_t)NN*96];
__device__ float g_GH2 [(size_t)NN*96];
__device__ float g_dinv[NN];
__device__ int   g_deg [NN];

__device__ __forceinline__ float leaky_f(float v) { return v > 0.f ? v : 0.01f * v; }
__device__ __forceinline__ float sigm_f(float x)  { return 1.f / (1.f + expf(-x)); }

// ---------------- generic register-tiled SGEMM ------------------------------
// C[M,Nn] = A[M,K] @ B[K,Nn]  (+ epilogue)
// MODE 0: C = leaky(acc + bias[col])
// MODE 1: C = acc + bias[col]
// MODE 2: C = acc*dinv[row]; C2 = acc*dinv[row]^2   (conv self-loop init)
template<int BM, int BN, int BK, int TM, int TN, int MODE>
__global__ void sgemm_k(const float* __restrict__ A, const float* __restrict__ B,
                        const float* __restrict__ bias, const float* __restrict__ dinv,
                        float* __restrict__ C, float* __restrict__ C2,
                        int M, int Nn, int K) {
    constexpr int THREADS = (BM / TM) * (BN / TN);
    __shared__ float As[BK][BM];
    __shared__ float Bs[BK][BN];

    const int tid  = threadIdx.x;
    const int tCol = tid % (BN / TN);
    const int tRow = tid / (BN / TN);
    const int bx = blockIdx.x, by = blockIdx.y;

    const float* Ab = A + (size_t)by * BM * K;
    const float* Bb = B + (size_t)bx * BN;

    constexpr int ALPR = BK / 4;            // float4 loads per A-tile row
    const int aRow0 = tid / ALPR;
    const int aCol  = (tid % ALPR) * 4;
    constexpr int ARS = THREADS / ALPR;

    constexpr int BLPR = BN / 4;            // float4 loads per B-tile row
    const int bRow0 = tid / BLPR;
    const int bCol  = (tid % BLPR) * 4;
    constexpr int BRS = THREADS / BLPR;

    float acc[TM][TN] = {};

    for (int k0 = 0; k0 < K; k0 += BK) {
        #pragma unroll
        for (int r = aRow0; r < BM; r += ARS) {
            int gr = by * BM + r;
            float4 v = make_float4(0.f, 0.f, 0.f, 0.f);
            if (gr < M)
                v = *reinterpret_cast<const float4*>(Ab + (size_t)r * K + k0 + aCol);
            As[aCol + 0][r] = v.x; As[aCol + 1][r] = v.y;
            As[aCol + 2][r] = v.z; As[aCol + 3][r] = v.w;
        }
        #pragma unroll
        for (int r = bRow0; r < BK; r += BRS) {
            *reinterpret_cast<float4*>(&Bs[r][bCol]) =
                *reinterpret_cast<const float4*>(Bb + (size_t)(k0 + r) * Nn + bCol);
        }
        __syncthreads();

        #pragma unroll
        for (int k = 0; k < BK; k++) {
            float ra[TM], rb[TN];
            #pragma unroll
            for (int i = 0; i < TM; i++) ra[i] = As[k][tRow * TM + i];
            #pragma unroll
            for (int j = 0; j < TN; j++) rb[j] = Bs[k][tCol * TN + j];
            #pragma unroll
            for (int i = 0; i < TM; i++)
                #pragma unroll
                for (int j = 0; j < TN; j++)
                    acc[i][j] += ra[i] * rb[j];
        }
        __syncthreads();
    }

    #pragma unroll
    for (int i = 0; i < TM; i++) {
        int gr = by * BM + tRow * TM + i;
        if (gr >= M) continue;
        float d = (MODE == 2) ? dinv[gr] : 0.f;
        #pragma unroll
        for (int j = 0; j < TN; j++) {
            int gc = bx * BN + tCol * TN + j;
            float v = acc[i][j];
            if (MODE == 0)      { v += bias[gc]; C[(size_t)gr * Nn + gc] = leaky_f(v); }
            else if (MODE == 1) { v += bias[gc]; C[(size_t)gr * Nn + gc] = v; }
            else {
                C [(size_t)gr * Nn + gc] = v * d;
                C2[(size_t)gr * Nn + gc] = v * d * d;
            }
        }
    }
}

// ---------------- degree / dinv ---------------------------------------------
__global__ void zero_deg_k(int* deg) {
    int i = blockIdx.x * blockDim.x + threadIdx.x;
    if (i < NN) deg[i] = 0;
}
__global__ void deg_k(const int* __restrict__ dst, int* __restrict__ deg) {
    int e = blockIdx.x * blockDim.x + threadIdx.x;
    if (e < NE) atomicAdd(&deg[dst[e]], 1);
}
__global__ void dinv_k(const int* __restrict__ deg, float* __restrict__ dinv) {
    int i = blockIdx.x * blockDim.x + threadIdx.x;
    if (i < NN) dinv[i] = rsqrtf((float)deg[i] + 1.0f);
}

// ---------------- edge scatter: AGG[dst] += HWd[src] * dinv[dst] ------------
template<int F>
__global__ void scatter_k(const int* __restrict__ src, const int* __restrict__ dst,
                          const float* __restrict__ HWd, const float* __restrict__ dinv,
                          float* __restrict__ AGG) {
    unsigned t = blockIdx.x * blockDim.x + threadIdx.x;
    if (t >= (unsigned)NE * F) return;
    int e = t / F, f = t % F;
    int s = src[e], d = dst[e];
    atomicAdd(&AGG[(size_t)d * F + f], HWd[(size_t)s * F + f] * dinv[d]);
}

// ---------------- elementwise: C = leaky(A + b[col]) ------------------------
__global__ void bias_leaky_k(const float* __restrict__ A, const float* __restrict__ b,
                             float* __restrict__ C, int H, int total) {
    int i = blockIdx.x * blockDim.x + threadIdx.x;
    if (i < total) {
        float v = A[i] + b[i % H];
        C[i] = leaky_f(v);
    }
}

// ---------------- GRU gating (+ optional row L2 normalize) ------------------
template<int H, bool NORM>
__global__ void gate_k(const float* __restrict__ GI, const float* __restrict__ GH,
                       const float* __restrict__ Hp, float* __restrict__ Out) {
    constexpr int NPB = 128 / H;
    __shared__ float sred[8];
    int tid = threadIdx.x;
    int ln = tid / H, j = tid % H;
    int node = blockIdx.x * NPB + ln;
    if (node >= NN) return;

    size_t g = (size_t)node * 3 * H + j;
    float r  = sigm_f(GI[g] + GH[g]);
    float z  = sigm_f(GI[g + H] + GH[g + H]);
    float nc = tanhf(GI[g + 2 * H] + r * GH[g + 2 * H]);
    float hp = Hp[(size_t)node * H + j];
    float h  = (1.f - z) * nc + z * hp;

    if constexpr (NORM) {  // H == 64: each node spans exactly 2 warps
        float sq = h * h;
        #pragma unroll
        for (int o = 16; o > 0; o >>= 1) sq += __shfl_xor_sync(0xffffffffu, sq, o);
        int warp = tid >> 5;
        if ((tid & 31) == 0) sred[warp] = sq;
        __syncthreads();
        float tot = sred[ln * 2] + sred[ln * 2 + 1];
        h *= rsqrtf(tot);
    }
    Out[(size_t)node * H + j] = h;
}

// ---------------- launcher ---------------------------------------------------
extern "C" void kernel_launch(void* const* d_in, const int* in_sizes, int n_in,
                              void* d_out, int out_size) {
    const float* x     = (const float*)d_in[0];
    const float* prev0 = (const float*)d_in[1];
    const float* prev1 = (const float*)d_in[2];
    const float* W_p1  = (const float*)d_in[3];
    const float* b_p1  = (const float*)d_in[4];
    const float* W_p2  = (const float*)d_in[5];
    const float* b_p2  = (const float*)d_in[6];
    const float* W_c1  = (const float*)d_in[7];
    const float* b_c1  = (const float*)d_in[8];
    const float* W_c2  = (const float*)d_in[9];
    const float* b_c2  = (const float*)d_in[10];
    const float* Wih1  = (const float*)d_in[11];
    const float* Whh1  = (const float*)d_in[12];
    const float* bih1  = (const float*)d_in[13];
    const float* bhh1  = (const float*)d_in[14];
    const float* Wih2  = (const float*)d_in[15];
    const float* Whh2  = (const float*)d_in[16];
    const float* bih2  = (const float*)d_in[17];
    const float* bhh2  = (const float*)d_in[18];
    const int*   src   = (const int*)d_in[19];
    const int*   dst   = (const int*)d_in[20];

    float* out  = (float*)d_out;
    float* emb0 = out + (size_t)NN * 32;   // output tuple (h[N,32], emb0[N,64]) flattened

    float *H0, *H1, *HW1, *AGG1, *GI1, *GH1, *HW2, *AGG2, *GI2, *GH2, *dinv;
    int* deg;
    cudaGetSymbolAddress((void**)&H0,   g_H0);
    cudaGetSymbolAddress((void**)&H1,   g_H1);
    cudaGetSymbolAddress((void**)&HW1,  g_HW1);
    cudaGetSymbolAddress((void**)&AGG1, g_AGG1);
    cudaGetSymbolAddress((void**)&GI1,  g_GI1);
    cudaGetSymbolAddress((void**)&GH1,  g_GH1);
    cudaGetSymbolAddress((void**)&HW2,  g_HW2);
    cudaGetSymbolAddress((void**)&AGG2, g_AGG2);
    cudaGetSymbolAddress((void**)&GI2,  g_GI2);
    cudaGetSymbolAddress((void**)&GH2,  g_GH2);
    cudaGetSymbolAddress((void**)&dinv, g_dinv);
    cudaGetSymbolAddress((void**)&deg,  g_deg);

    const int MB = (NN + 127) / 128;   // 782 row-blocks

    // degrees -> dinv
    zero_deg_k<<<(NN + 255) / 256, 256>>>(deg);
    deg_k<<<(NE + 255) / 256, 256>>>(dst, deg);
    dinv_k<<<(NN + 255) / 256, 256>>>(deg, dinv);

    // preprocess MLP
    { dim3 g(2, MB); sgemm_k<128,128,16,8,8,0><<<g, 256>>>(x,  W_p1, b_p1, nullptr, H0, nullptr, NN, 256, 256); }
    { dim3 g(1, MB); sgemm_k<128,128,16,8,8,0><<<g, 256>>>(H0, W_p2, b_p2, nullptr, H1, nullptr, NN, 128, 256); }

    // conv1: hw*dinv (HW1) + self-loop init (AGG1), then edge scatter, then bias+leaky
    { dim3 g(1, MB); sgemm_k<128,64,16,8,4,2><<<g, 256>>>(H1, W_c1, nullptr, dinv, HW1, AGG1, NN, 64, 128); }
    scatter_k<64><<<((unsigned)NE * 64 + 255) / 256, 256>>>(src, dst, HW1, dinv, AGG1);
    bias_leaky_k<<<(NN * 64 + 255) / 256, 256>>>(AGG1, b_c1, HW1, 64, NN * 64);

    // GRU1 gates + gating + L2 normalize -> emb0 (second output, also conv2 input)
    { dim3 g(3, MB); sgemm_k<128,64,16,8,4,1><<<g, 256>>>(HW1,   Wih1, bih1, nullptr, GI1, nullptr, NN, 192, 64); }
    { dim3 g(3, MB); sgemm_k<128,64,16,8,4,1><<<g, 256>>>(prev0, Whh1, bhh1, nullptr, GH1, nullptr, NN, 192, 64); }
    gate_k<64, true><<<NN / 2, 128>>>(GI1, GH1, prev0, emb0);

    // conv2
    { dim3 g(1, MB); sgemm_k<128,32,16,8,4,2><<<g, 128>>>(emb0, W_c2, nullptr, dinv, HW2, AGG2, NN, 32, 64); }
    scatter_k<32><<<((unsigned)NE * 32 + 255) / 256, 256>>>(src, dst, HW2, dinv, AGG2);
    bias_leaky_k<<<(NN * 32 + 255) / 256, 256>>>(AGG2, b_c2, HW2, 32, NN * 32);

    // GRU2 gates + gating -> h (first output)
    { dim3 g(3, MB); sgemm_k<128,32,16,8,4,1><<<g, 128>>>(HW2,  Wih2, bih2, nullptr, GI2, nullptr, NN, 96, 32); }
    { dim3 g(3, MB); sgemm_k<128,32,16,8,4,1><<<g, 128>>>(prev1, Whh2, bhh2, nullptr, GH2, nullptr, NN, 96, 32); }
    gate_k<32, false><<<NN / 4, 128>>>(GI2, GH2, prev1, out);
}

// round 2
// speedup vs baseline: 1.1871x; 1.1871x over previous
#include <cuda_runtime.h>
#include <math.h>

#define NN 100000
#define NE 1600000

// ---------------- scratch (static device globals; no runtime allocation) ----
__device__ float g_H0  [(size_t)NN*256];
__device__ float g_H1  [(size_t)NN*128];
__device__ float g_HW1 [(size_t)NN*64];   // hw1 * dinv[row]
__device__ float g_C1  [(size_t)NN*64];   // conv1 activated output
__device__ float g_GI1 [(size_t)NN*192];
__device__ float g_GH1 [(size_t)NN*192];
__device__ float g_HW2 [(size_t)NN*32];   // hw2 * dinv[row]
__device__ float g_C2  [(size_t)NN*32];   // conv2 activated output
__device__ float g_GI2 [(size_t)NN*96];
__device__ float g_GH2 [(size_t)NN*96];
__device__ float g_dinv[NN];
__device__ int   g_deg [NN];
__device__ int   g_off [NN];
__device__ int   g_cur [NN];
__device__ int   g_csr [NE];

__device__ __forceinline__ float leaky_f(float v) { return v > 0.f ? v : 0.01f * v; }
__device__ __forceinline__ float sigm_f(float x)  { return 1.f / (1.f + expf(-x)); }

// ---------------- generic register-tiled SGEMM ------------------------------
// C[M,Nn] = A[M,K] @ B[K,Nn]  (+ epilogue)
// MODE 0: C = leaky(acc + bias[col])
// MODE 1: C = acc + bias[col]
// MODE 2: C = acc * dinv[row]
template<int BM, int BN, int BK, int TM, int TN, int MODE>
__global__ void sgemm_k(const float* __restrict__ A, const float* __restrict__ B,
                        const float* __restrict__ bias, const float* __restrict__ dinv,
                        float* __restrict__ C,
                        int M, int Nn, int K) {
    constexpr int THREADS = (BM / TM) * (BN / TN);
    __shared__ float As[BK][BM];
    __shared__ float Bs[BK][BN];

    const int tid  = threadIdx.x;
    const int tCol = tid % (BN / TN);
    const int tRow = tid / (BN / TN);
    const int bx = blockIdx.x, by = blockIdx.y;

    const float* Ab = A + (size_t)by * BM * K;
    const float* Bb = B + (size_t)bx * BN;

    constexpr int ALPR = BK / 4;            // float4 loads per A-tile row
    const int aRow0 = tid / ALPR;
    const int aCol  = (tid % ALPR) * 4;
    constexpr int ARS = THREADS / ALPR;

    constexpr int BLPR = BN / 4;            // float4 loads per B-tile row
    const int bRow0 = tid / BLPR;
    const int bCol  = (tid % BLPR) * 4;
    constexpr int BRS = THREADS / BLPR;

    float acc[TM][TN] = {};

    for (int k0 = 0; k0 < K; k0 += BK) {
        #pragma unroll
        for (int r = aRow0; r < BM; r += ARS) {
            int gr = by * BM + r;
            float4 v = make_float4(0.f, 0.f, 0.f, 0.f);
            if (gr < M)
                v = *reinterpret_cast<const float4*>(Ab + (size_t)r * K + k0 + aCol);
            As[aCol + 0][r] = v.x; As[aCol + 1][r] = v.y;
            As[aCol + 2][r] = v.z; As[aCol + 3][r] = v.w;
        }
        #pragma unroll
        for (int r = bRow0; r < BK; r += BRS) {
            *reinterpret_cast<float4*>(&Bs[r][bCol]) =
                *reinterpret_cast<const float4*>(Bb + (size_t)(k0 + r) * Nn + bCol);
        }
        __syncthreads();

        #pragma unroll
        for (int k = 0; k < BK; k++) {
            float ra[TM], rb[TN];
            #pragma unroll
            for (int i = 0; i < TM; i++) ra[i] = As[k][tRow * TM + i];
            #pragma unroll
            for (int j = 0; j < TN; j++) rb[j] = Bs[k][tCol * TN + j];
            #pragma unroll
            for (int i = 0; i < TM; i++)
                #pragma unroll
                for (int j = 0; j < TN; j++)
                    acc[i][j] += ra[i] * rb[j];
        }
        __syncthreads();
    }

    #pragma unroll
    for (int i = 0; i < TM; i++) {
        int gr = by * BM + tRow * TM + i;
        if (gr >= M) continue;
        float d = (MODE == 2) ? dinv[gr] : 0.f;
        #pragma unroll
        for (int j = 0; j < TN; j++) {
            int gc = bx * BN + tCol * TN + j;
            float v = acc[i][j];
            if (MODE == 0)      { v += bias[gc]; C[(size_t)gr * Nn + gc] = leaky_f(v); }
            else if (MODE == 1) { v += bias[gc]; C[(size_t)gr * Nn + gc] = v; }
            else                { C[(size_t)gr * Nn + gc] = v * d; }
        }
    }
}

// ---------------- degree / dinv ---------------------------------------------
__global__ void zero_deg_k(int* deg) {
    int i = blockIdx.x * blockDim.x + threadIdx.x;
    if (i < NN) deg[i] = 0;
}
__global__ void deg_k(const int* __restrict__ dst, int* __restrict__ deg) {
    int e = blockIdx.x * blockDim.x + threadIdx.x;
    if (e < NE) atomicAdd(&deg[dst[e]], 1);
}
__global__ void dinv_k(const int* __restrict__ deg, float* __restrict__ dinv) {
    int i = blockIdx.x * blockDim.x + threadIdx.x;
    if (i < NN) dinv[i] = rsqrtf((float)deg[i] + 1.0f);
}

// ---------------- CSR build --------------------------------------------------
// single-block exclusive scan of deg -> off (and cur copy). 1024 thr, 98 elem each.
__global__ void scan_k(const int* __restrict__ deg, int* __restrict__ off,
                       int* __restrict__ cur) {
    __shared__ int s[1024];
    const int CH = 98;                       // 1024*98 >= 100000
    int t = threadIdx.x;
    int base = t * CH;
    int sum = 0;
    for (int i = 0; i < CH; i++) {
        int idx = base + i;
        if (idx < NN) sum += deg[idx];
    }
    s[t] = sum;
    __syncthreads();
    for (int o = 1; o < 1024; o <<= 1) {     // Hillis-Steele inclusive scan
        int v = (t >= o) ? s[t - o] : 0;
        __syncthreads();
        s[t] += v;
        __syncthreads();
    }
    int run = (t > 0) ? s[t - 1] : 0;        // exclusive prefix for this chunk
    for (int i = 0; i < CH; i++) {
        int idx = base + i;
        if (idx < NN) {
            off[idx] = run;
            cur[idx] = run;
            run += deg[idx];
        }
    }
}

__global__ void fill_k(const int* __restrict__ src, const int* __restrict__ dst,
                       int* __restrict__ cur, int* __restrict__ csr) {
    int e = blockIdx.x * blockDim.x + threadIdx.x;
    if (e < NE) {
        int pos = atomicAdd(&cur[dst[e]], 1);
        csr[pos] = src[e];
    }
}

// ---------------- CSR gather: fused conv aggregation + self-loop + bias + leaky
// Out[n][f] = leaky( dinv[n] * ( sum_{s in nbr(n)} HWd[s][f]  +  HWd[n][f] ) + bias[f] )
template<int F>
__global__ void gather_k(const int* __restrict__ off, const int* __restrict__ deg,
                         const int* __restrict__ csr, const float* __restrict__ HWd,
                         const float* __restrict__ dinv, const float* __restrict__ bias,
                         float* __restrict__ Out) {
    constexpr int NPB = 256 / F;
    int tid = threadIdx.x;
    int ln = tid / F, f = tid % F;
    int n = blockIdx.x * NPB + ln;
    if (n >= NN) return;

    int s0 = off[n], cnt = deg[n];
    float a0 = 0.f, a1 = 0.f, a2 = 0.f, a3 = 0.f;
    int i = 0;
    for (; i + 4 <= cnt; i += 4) {
        int e0 = csr[s0 + i], e1 = csr[s0 + i + 1];
        int e2 = csr[s0 + i + 2], e3 = csr[s0 + i + 3];
        a0 += HWd[(size_t)e0 * F + f];
        a1 += HWd[(size_t)e1 * F + f];
        a2 += HWd[(size_t)e2 * F + f];
        a3 += HWd[(size_t)e3 * F + f];
    }
    for (; i < cnt; i++) a0 += HWd[(size_t)csr[s0 + i] * F + f];

    float sum = (a0 + a1) + (a2 + a3);
    float v = dinv[n] * (sum + HWd[(size_t)n * F + f]) + bias[f];
    Out[(size_t)n * F + f] = leaky_f(v);
}

// ---------------- GRU gating (+ optional row L2 normalize) ------------------
template<int H, bool NORM>
__global__ void gate_k(const float* __restrict__ GI, const float* __restrict__ GH,
                       const float* __restrict__ Hp, float* __restrict__ Out) {
    constexpr int NPB = 128 / H;
    __shared__ float sred[8];
    int tid = threadIdx.x;
    int ln = tid / H, j = tid % H;
    int node = blockIdx.x * NPB + ln;
    if (node >= NN) return;

    size_t g = (size_t)node * 3 * H + j;
    float r  = sigm_f(GI[g] + GH[g]);
    float z  = sigm_f(GI[g + H] + GH[g + H]);
    float nc = tanhf(GI[g + 2 * H] + r * GH[g + 2 * H]);
    float hp = Hp[(size_t)node * H + j];
    float h  = (1.f - z) * nc + z * hp;

    if constexpr (NORM) {  // H == 64: each node spans exactly 2 warps
        float sq = h * h;
        #pragma unroll
        for (int o = 16; o > 0; o >>= 1) sq += __shfl_xor_sync(0xffffffffu, sq, o);
        int warp = tid >> 5;
        if ((tid & 31) == 0) sred[warp] = sq;
        __syncthreads();
        float tot = sred[ln * 2] + sred[ln * 2 + 1];
        h *= rsqrtf(tot);
    }
    Out[(size_t)node * H + j] = h;
}

// ---------------- launcher ---------------------------------------------------
extern "C" void kernel_launch(void* const* d_in, const int* in_sizes, int n_in,
                              void* d_out, int out_size) {
    const float* x     = (const float*)d_in[0];
    const float* prev0 = (const float*)d_in[1];
    const float* prev1 = (const float*)d_in[2];
    const float* W_p1  = (const float*)d_in[3];
    const float* b_p1  = (const float*)d_in[4];
    const float* W_p2  = (const float*)d_in[5];
    const float* b_p2  = (const float*)d_in[6];
    const float* W_c1  = (const float*)d_in[7];
    const float* b_c1  = (const float*)d_in[8];
    const float* W_c2  = (const float*)d_in[9];
    const float* b_c2  = (const float*)d_in[10];
    const float* Wih1  = (const float*)d_in[11];
    const float* Whh1  = (const float*)d_in[12];
    const float* bih1  = (const float*)d_in[13];
    const float* bhh1  = (const float*)d_in[14];
    const float* Wih2  = (const float*)d_in[15];
    const float* Whh2  = (const float*)d_in[16];
    const float* bih2  = (const float*)d_in[17];
    const float* bhh2  = (const float*)d_in[18];
    const int*   src   = (const int*)d_in[19];
    const int*   dst   = (const int*)d_in[20];

    float* out  = (float*)d_out;
    float* emb0 = out + (size_t)NN * 32;   // output tuple (h[N,32], emb0[N,64]) flattened

    float *H0, *H1, *HW1, *C1, *GI1, *GH1, *HW2, *C2, *GI2, *GH2, *dinv;
    int *deg, *off, *cur, *csr;
    cudaGetSymbolAddress((void**)&H0,   g_H0);
    cudaGetSymbolAddress((void**)&H1,   g_H1);
    cudaGetSymbolAddress((void**)&HW1,  g_HW1);
    cudaGetSymbolAddress((void**)&C1,   g_C1);
    cudaGetSymbolAddress((void**)&GI1,  g_GI1);
    cudaGetSymbolAddress((void**)&GH1,  g_GH1);
    cudaGetSymbolAddress((void**)&HW2,  g_HW2);
    cudaGetSymbolAddress((void**)&C2,   g_C2);
    cudaGetSymbolAddress((void**)&GI2,  g_GI2);
    cudaGetSymbolAddress((void**)&GH2,  g_GH2);
    cudaGetSymbolAddress((void**)&dinv, g_dinv);
    cudaGetSymbolAddress((void**)&deg,  g_deg);
    cudaGetSymbolAddress((void**)&off,  g_off);
    cudaGetSymbolAddress((void**)&cur,  g_cur);
    cudaGetSymbolAddress((void**)&csr,  g_csr);

    const int MB = (NN + 127) / 128;   // 782 row-blocks

    // degrees -> dinv, CSR build (reused by both conv layers)
    zero_deg_k<<<(NN + 255) / 256, 256>>>(deg);
    deg_k<<<(NE + 255) / 256, 256>>>(dst, deg);
    dinv_k<<<(NN + 255) / 256, 256>>>(deg, dinv);
    scan_k<<<1, 1024>>>(deg, off, cur);
    fill_k<<<(NE + 255) / 256, 256>>>(src, dst, cur, csr);

    // preprocess MLP
    { dim3 g(2, MB); sgemm_k<128,128,16,8,8,0><<<g, 256>>>(x,  W_p1, b_p1, nullptr, H0, NN, 256, 256); }
    { dim3 g(1, MB); sgemm_k<128,128,16,8,8,0><<<g, 256>>>(H0, W_p2, b_p2, nullptr, H1, NN, 128, 256); }

    // conv1: hw*dinv (HW1), then CSR gather (fused self-loop + bias + leaky)
    { dim3 g(1, MB); sgemm_k<128,64,16,8,4,2><<<g, 256>>>(H1, W_c1, nullptr, dinv, HW1, NN, 64, 128); }
    gather_k<64><<<(NN + 3) / 4, 256>>>(off, deg, csr, HW1, dinv, b_c1, C1);

    // GRU1 gates + gating + L2 normalize -> emb0 (second output, also conv2 input)
    { dim3 g(3, MB); sgemm_k<128,64,16,8,4,1><<<g, 256>>>(C1,    Wih1, bih1, nullptr, GI1, NN, 192, 64); }
    { dim3 g(3, MB); sgemm_k<128,64,16,8,4,1><<<g, 256>>>(prev0, Whh1, bhh1, nullptr, GH1, NN, 192, 64); }
    gate_k<64, true><<<NN / 2, 128>>>(GI1, GH1, prev0, emb0);

    // conv2
    { dim3 g(1, MB); sgemm_k<128,32,16,8,4,2><<<g, 128>>>(emb0, W_c2, nullptr, dinv, HW2, NN, 32, 64); }
    gather_k<32><<<(NN + 7) / 8, 256>>>(off, deg, csr, HW2, dinv, b_c2, C2);

    // GRU2 gates + gating -> h (first output)
    { dim3 g(3, MB); sgemm_k<128,32,16,8,4,1><<<g, 128>>>(C2,   Wih2, bih2, nullptr, GI2, NN, 96, 32); }
    { dim3 g(3, MB); sgemm_k<128,32,16,8,4,1><<<g, 128>>>(prev1, Whh2, bhh2, nullptr, GH2, NN, 96, 32); }
    gate_k<32, false><<<NN / 4, 128>>>(GI2, GH2, prev1, out);
}

// round 4
// speedup vs baseline: 1.6196x; 1.3642x over previous
#include <cuda_runtime.h>
#include <math.h>
#include <stdint.h>

#define NN 100000
#define NE 1600000

// ---------------- scratch (static device globals; no runtime allocation) ----
__device__ float g_H0  [(size_t)NN*256];
__device__ float g_H1  [(size_t)NN*128];
__device__ float g_HW1 [(size_t)NN*64];   // hw1 * dinv[row]
__device__ float g_C1  [(size_t)NN*64];   // conv1 activated output
__device__ float g_GI1 [(size_t)NN*192];
__device__ float g_GH1 [(size_t)NN*192];
__device__ float g_HW2 [(size_t)NN*32];   // hw2 * dinv[row]
__device__ float g_C2  [(size_t)NN*32];   // conv2 activated output
__device__ float g_GI2 [(size_t)NN*96];
__device__ float g_GH2 [(size_t)NN*96];
__device__ float g_dinv[NN];
__device__ int   g_deg [NN];
__device__ int   g_off [NN];
__device__ int   g_cur [NN];
__device__ int   g_csr [NE];
__device__ int   g_bsum[512];

__device__ __forceinline__ float leaky_f(float v) { return v > 0.f ? v : 0.01f * v; }
__device__ __forceinline__ float sigm_f(float x)  { return 1.f / (1.f + expf(-x)); }

__device__ __forceinline__ uint32_t f2tf32(float f) {
    uint32_t r;
    asm("cvt.rna.tf32.f32 %0, %1;" : "=r"(r) : "f"(f));
    return r;
}
__device__ __forceinline__ void mma_tf32(float c[4], const uint32_t a[4],
                                         uint32_t b0, uint32_t b1) {
    asm("mma.sync.aligned.m16n8k8.row.col.f32.tf32.tf32.f32 "
        "{%0,%1,%2,%3},{%4,%5,%6,%7},{%8,%9},{%0,%1,%2,%3};"
        : "+f"(c[0]), "+f"(c[1]), "+f"(c[2]), "+f"(c[3])
        : "r"(a[0]), "r"(a[1]), "r"(a[2]), "r"(a[3]), "r"(b0), "r"(b1));
}

// ---------------- TF32 tensor-core GEMM (3xTF32 compensated) -----------------
// C[M,N] = leaky(A[M,K] @ B[K,N] + bias[col]).  BM=128, BN=128, BK=16.
// 256 threads = 8 warps (4 along M x 2 along N); warp tile 32x64.
__global__ void __launch_bounds__(256, 2)
tf32gemm_k(const float* __restrict__ A, const float* __restrict__ B,
           const float* __restrict__ bias, float* __restrict__ C,
           int M, int N, int K) {
    __shared__ float Ah[128][20], Al[128][20];     // pad 20: conflict-free frags
    __shared__ float Bh[16][136], Bl[16][136];     // pad 136 (mod 32 == 8)

    const int t    = threadIdx.x;
    const int lane = t & 31, wid = t >> 5;
    const int g    = lane >> 2, tg = lane & 3;
    const int wm   = (wid & 3) * 32;               // warp M offset in tile
    const int wn   = (wid >> 2) * 64;              // warp N offset in tile
    const int bx = blockIdx.x, by = blockIdx.y;

    float acc[2][8][4];
    #pragma unroll
    for (int i = 0; i < 2; i++)
        #pragma unroll
        for (int j = 0; j < 8; j++)
            #pragma unroll
            for (int q = 0; q < 4; q++) acc[i][j][q] = 0.f;

    for (int k0 = 0; k0 < K; k0 += 16) {
        __syncthreads();
        // stage A tile (128x16): 512 float4, 2 per thread
        #pragma unroll
        for (int p = t; p < 512; p += 256) {
            int row = p >> 2, kc = (p & 3) * 4;
            int gr = by * 128 + row;
            float4 v = make_float4(0.f, 0.f, 0.f, 0.f);
            if (gr < M) v = *reinterpret_cast<const float4*>(A + (size_t)gr * K + k0 + kc);
            float4 h, l;
            h.x = __uint_as_float(f2tf32(v.x)); l.x = v.x - h.x;
            h.y = __uint_as_float(f2tf32(v.y)); l.y = v.y - h.y;
            h.z = __uint_as_float(f2tf32(v.z)); l.z = v.z - h.z;
            h.w = __uint_as_float(f2tf32(v.w)); l.w = v.w - h.w;
            *reinterpret_cast<float4*>(&Ah[row][kc]) = h;
            *reinterpret_cast<float4*>(&Al[row][kc]) = l;
        }
        // stage B tile (16x128): 512 float4, 2 per thread
        #pragma unroll
        for (int p = t; p < 512; p += 256) {
            int krow = p >> 5, n = (p & 31) * 4;
            float4 v = *reinterpret_cast<const float4*>(
                B + (size_t)(k0 + krow) * N + bx * 128 + n);
            float4 h, l;
            h.x = __uint_as_float(f2tf32(v.x)); l.x = v.x - h.x;
            h.y = __uint_as_float(f2tf32(v.y)); l.y = v.y - h.y;
            h.z = __uint_as_float(f2tf32(v.z)); l.z = v.z - h.z;
            h.w = __uint_as_float(f2tf32(v.w)); l.w = v.w - h.w;
            *reinterpret_cast<float4*>(&Bh[krow][n]) = h;
            *reinterpret_cast<float4*>(&Bl[krow][n]) = l;
        }
        __syncthreads();

        #pragma unroll
        for (int s = 0; s < 16; s += 8) {
            uint32_t ah[2][4], al[2][4];
            #pragma unroll
            for (int i = 0; i < 2; i++) {
                int r0 = wm + i * 16 + g;
                ah[i][0] = __float_as_uint(Ah[r0    ][s + tg    ]);
                ah[i][1] = __float_as_uint(Ah[r0 + 8][s + tg    ]);
                ah[i][2] = __float_as_uint(Ah[r0    ][s + tg + 4]);
                ah[i][3] = __float_as_uint(Ah[r0 + 8][s + tg + 4]);
                al[i][0] = __float_as_uint(Al[r0    ][s + tg    ]);
                al[i][1] = __float_as_uint(Al[r0 + 8][s + tg    ]);
                al[i][2] = __float_as_uint(Al[r0    ][s + tg + 4]);
                al[i][3] = __float_as_uint(Al[r0 + 8][s + tg + 4]);
            }
            #pragma unroll
            for (int j = 0; j < 8; j++) {
                int cb = wn + j * 8 + g;
                uint32_t b0h = __float_as_uint(Bh[s + tg    ][cb]);
                uint32_t b1h = __float_as_uint(Bh[s + tg + 4][cb]);
                uint32_t b0l = __float_as_uint(Bl[s + tg    ][cb]);
                uint32_t b1l = __float_as_uint(Bl[s + tg + 4][cb]);
                #pragma unroll
                for (int i = 0; i < 2; i++) {
                    mma_tf32(acc[i][j], ah[i], b0h, b1h);   // hi*hi
                    mma_tf32(acc[i][j], al[i], b0h, b1h);   // lo*hi
                    mma_tf32(acc[i][j], ah[i], b0l, b1l);   // hi*lo
                }
            }
        }
    }

    // epilogue: bias + leaky
    #pragma unroll
    for (int i = 0; i < 2; i++) {
        int gr0 = by * 128 + wm + i * 16 + g;
        #pragma unroll
        for (int j = 0; j < 8; j++) {
            int gc = bx * 128 + wn + j * 8 + 2 * tg;
            float b0 = bias[gc], b1 = bias[gc + 1];
            if (gr0 < M) {
                float2 v = make_float2(leaky_f(acc[i][j][0] + b0),
                                       leaky_f(acc[i][j][1] + b1));
                *reinterpret_cast<float2*>(C + (size_t)gr0 * N + gc) = v;
            }
            if (gr0 + 8 < M) {
                float2 v = make_float2(leaky_f(acc[i][j][2] + b0),
                                       leaky_f(acc[i][j][3] + b1));
                *reinterpret_cast<float2*>(C + (size_t)(gr0 + 8) * N + gc) = v;
            }
        }
    }
}

// ---------------- generic register-tiled SGEMM (small-N layers) -------------
// MODE 1: C = acc + bias[col];  MODE 2: C = acc * dinv[row]
template<int BM, int BN, int BK, int TM, int TN, int MODE>
__global__ void sgemm_k(const float* __restrict__ A, const float* __restrict__ B,
                        const float* __restrict__ bias, const float* __restrict__ dinv,
                        float* __restrict__ C,
                        int M, int Nn, int K) {
    constexpr int THREADS = (BM / TM) * (BN / TN);
    __shared__ float As[BK][BM];
    __shared__ float Bs[BK][BN];

    const int tid  = threadIdx.x;
    const int tCol = tid % (BN / TN);
    const int tRow = tid / (BN / TN);
    const int bx = blockIdx.x, by = blockIdx.y;

    const float* Ab = A + (size_t)by * BM * K;
    const float* Bb = B + (size_t)bx * BN;

    constexpr int ALPR = BK / 4;
    const int aRow0 = tid / ALPR;
    const int aCol  = (tid % ALPR) * 4;
    constexpr int ARS = THREADS / ALPR;

    constexpr int BLPR = BN / 4;
    const int bRow0 = tid / BLPR;
    const int bCol  = (tid % BLPR) * 4;
    constexpr int BRS = THREADS / BLPR;

    float acc[TM][TN] = {};

    for (int k0 = 0; k0 < K; k0 += BK) {
        #pragma unroll
        for (int r = aRow0; r < BM; r += ARS) {
            int gr = by * BM + r;
            float4 v = make_float4(0.f, 0.f, 0.f, 0.f);
            if (gr < M)
                v = *reinterpret_cast<const float4*>(Ab + (size_t)r * K + k0 + aCol);
            As[aCol + 0][r] = v.x; As[aCol + 1][r] = v.y;
            As[aCol + 2][r] = v.z; As[aCol + 3][r] = v.w;
        }
        #pragma unroll
        for (int r = bRow0; r < BK; r += BRS) {
            *reinterpret_cast<float4*>(&Bs[r][bCol]) =
                *reinterpret_cast<const float4*>(Bb + (size_t)(k0 + r) * Nn + bCol);
        }
        __syncthreads();

        #pragma unroll
        for (int k = 0; k < BK; k++) {
            float ra[TM], rb[TN];
            #pragma unroll
            for (int i = 0; i < TM; i++) ra[i] = As[k][tRow * TM + i];
            #pragma unroll
            for (int j = 0; j < TN; j++) rb[j] = Bs[k][tCol * TN + j];
            #pragma unroll
            for (int i = 0; i < TM; i++)
                #pragma unroll
                for (int j = 0; j < TN; j++)
                    acc[i][j] += ra[i] * rb[j];
        }
        __syncthreads();
    }

    #pragma unroll
    for (int i = 0; i < TM; i++) {
        int gr = by * BM + tRow * TM + i;
        if (gr >= M) continue;
        float d = (MODE == 2) ? dinv[gr] : 0.f;
        #pragma unroll
        for (int j = 0; j < TN; j++) {
            int gc = bx * BN + tCol * TN + j;
            float v = acc[i][j];
            if (MODE == 1) { v += bias[gc]; C[(size_t)gr * Nn + gc] = v; }
            else           { C[(size_t)gr * Nn + gc] = v * d; }
        }
    }
}

// ---------------- degree / dinv ---------------------------------------------
__global__ void zero_deg_k(int* deg) {
    int i = blockIdx.x * blockDim.x + threadIdx.x;
    if (i < NN) deg[i] = 0;
}
__global__ void deg_k(const int* __restrict__ dst, int* __restrict__ deg) {
    int e = blockIdx.x * blockDim.x + threadIdx.x;
    if (e < NE) atomicAdd(&deg[dst[e]], 1);
}
__global__ void dinv_k(const int* __restrict__ deg, float* __restrict__ dinv) {
    int i = blockIdx.x * blockDim.x + threadIdx.x;
    if (i < NN) dinv[i] = rsqrtf((float)deg[i] + 1.0f);
}

// ---------------- parallel CSR prefix sum (3 kernels) ------------------------
__global__ void scan_part_k(const int* __restrict__ deg, int* __restrict__ bsum) {
    __shared__ int s[256];
    int t = threadIdx.x;
    int i = blockIdx.x * 256 + t;
    s[t] = (i < NN) ? deg[i] : 0;
    __syncthreads();
    for (int o = 128; o > 0; o >>= 1) {
        if (t < o) s[t] += s[t + o];
        __syncthreads();
    }
    if (t == 0) bsum[blockIdx.x] = s[0];
}
__global__ void scan_top_k(int* __restrict__ bsum, int nb) {
    __shared__ int s[512];
    int t = threadIdx.x;
    int v = (t < nb) ? bsum[t] : 0;
    s[t] = v;
    __syncthreads();
    for (int o = 1; o < 512; o <<= 1) {
        int u = (t >= o) ? s[t - o] : 0;
        __syncthreads();
        s[t] += u;
        __syncthreads();
    }
    if (t < nb) bsum[t] = s[t] - v;   // exclusive
}
__global__ void scan_final_k(const int* __restrict__ deg, const int* __restrict__ bsum,
                             int* __restrict__ off, int* __restrict__ cur) {
    __shared__ int s[256];
    int t = threadIdx.x;
    int i = blockIdx.x * 256 + t;
    int d = (i < NN) ? deg[i] : 0;
    s[t] = d;
    __syncthreads();
    for (int o = 1; o < 256; o <<= 1) {
        int u = (t >= o) ? s[t - o] : 0;
        __syncthreads();
        s[t] += u;
        __syncthreads();
    }
    if (i < NN) {
        int o_ = bsum[blockIdx.x] + s[t] - d;
        off[i] = o_;
        cur[i] = o_;
    }
}

__global__ void fill_k(const int* __restrict__ src, const int* __restrict__ dst,
                       int* __restrict__ cur, int* __restrict__ csr) {
    int e = blockIdx.x * blockDim.x + threadIdx.x;
    if (e < NE) {
        int pos = atomicAdd(&cur[dst[e]], 1);
        csr[pos] = src[e];
    }
}

// ---------------- CSR gather: fused conv agg + self-loop + bias + leaky -----
template<int F>
__global__ void gather_k(const int* __restrict__ off, const int* __restrict__ deg,
                         const int* __restrict__ csr, const float* __restrict__ HWd,
                         const float* __restrict__ dinv, const float* __restrict__ bias,
                         float* __restrict__ Out) {
    constexpr int NPB = 256 / F;
    int tid = threadIdx.x;
    int ln = tid / F, f = tid % F;
    int n = blockIdx.x * NPB + ln;
    if (n >= NN) return;

    int s0 = off[n], cnt = deg[n];
    float a0 = 0.f, a1 = 0.f, a2 = 0.f, a3 = 0.f;
    int i = 0;
    for (; i + 4 <= cnt; i += 4) {
        int e0 = csr[s0 + i], e1 = csr[s0 + i + 1];
        int e2 = csr[s0 + i + 2], e3 = csr[s0 + i + 3];
        a0 += HWd[(size_t)e0 * F + f];
        a1 += HWd[(size_t)e1 * F + f];
        a2 += HWd[(size_t)e2 * F + f];
        a3 += HWd[(size_t)e3 * F + f];
    }
    for (; i < cnt; i++) a0 += HWd[(size_t)csr[s0 + i] * F + f];

    float sum = (a0 + a1) + (a2 + a3);
    float v = dinv[n] * (sum + HWd[(size_t)n * F + f]) + bias[f];
    Out[(size_t)n * F + f] = leaky_f(v);
}

// ---------------- GRU gating (+ optional row L2 normalize) ------------------
template<int H, bool NORM>
__global__ void gate_k(const float* __restrict__ GI, const float* __restrict__ GH,
                       const float* __restrict__ Hp, float* __restrict__ Out) {
    constexpr int NPB = 128 / H;
    __shared__ float sred[8];
    int tid = threadIdx.x;
    int ln = tid / H, j = tid % H;
    int node = blockIdx.x * NPB + ln;
    if (node >= NN) return;

    size_t g = (size_t)node * 3 * H + j;
    float r  = sigm_f(GI[g] + GH[g]);
    float z  = sigm_f(GI[g + H] + GH[g + H]);
    float nc = tanhf(GI[g + 2 * H] + r * GH[g + 2 * H]);
    float hp = Hp[(size_t)node * H + j];
    float h  = (1.f - z) * nc + z * hp;

    if constexpr (NORM) {
        float sq = h * h;
        #pragma unroll
        for (int o = 16; o > 0; o >>= 1) sq += __shfl_xor_sync(0xffffffffu, sq, o);
        int warp = tid >> 5;
        if ((tid & 31) == 0) sred[warp] = sq;
        __syncthreads();
        float tot = sred[ln * 2] + sred[ln * 2 + 1];
        h *= rsqrtf(tot);
    }
    Out[(size_t)node * H + j] = h;
}

// ---------------- launcher ---------------------------------------------------
extern "C" void kernel_launch(void* const* d_in, const int* in_sizes, int n_in,
                              void* d_out, int out_size) {
    const float* x     = (const float*)d_in[0];
    const float* prev0 = (const float*)d_in[1];
    const float* prev1 = (const float*)d_in[2];
    const float* W_p1  = (const float*)d_in[3];
    const float* b_p1  = (const float*)d_in[4];
    const float* W_p2  = (const float*)d_in[5];
    const float* b_p2  = (const float*)d_in[6];
    const float* W_c1  = (const float*)d_in[7];
    const float* b_c1  = (const float*)d_in[8];
    const float* W_c2  = (const float*)d_in[9];
    const float* b_c2  = (const float*)d_in[10];
    const float* Wih1  = (const float*)d_in[11];
    const float* Whh1  = (const float*)d_in[12];
    const float* bih1  = (const float*)d_in[13];
    const float* bhh1  = (const float*)d_in[14];
    const float* Wih2  = (const float*)d_in[15];
    const float* Whh2  = (const float*)d_in[16];
    const float* bih2  = (const float*)d_in[17];
    const float* bhh2  = (const float*)d_in[18];
    const int*   src   = (const int*)d_in[19];
    const int*   dst   = (const int*)d_in[20];

    float* out  = (float*)d_out;
    float* emb0 = out + (size_t)NN * 32;   // output tuple (h[N,32], emb0[N,64]) flattened

    float *H0, *H1, *HW1, *C1, *GI1, *GH1, *HW2, *C2, *GI2, *GH2, *dinv;
    int *deg, *off, *cur, *csr, *bsum;
    cudaGetSymbolAddress((void**)&H0,   g_H0);
    cudaGetSymbolAddress((void**)&H1,   g_H1);
    cudaGetSymbolAddress((void**)&HW1,  g_HW1);
    cudaGetSymbolAddress((void**)&C1,   g_C1);
    cudaGetSymbolAddress((void**)&GI1,  g_GI1);
    cudaGetSymbolAddress((void**)&GH1,  g_GH1);
    cudaGetSymbolAddress((void**)&HW2,  g_HW2);
    cudaGetSymbolAddress((void**)&C2,   g_C2);
    cudaGetSymbolAddress((void**)&GI2,  g_GI2);
    cudaGetSymbolAddress((void**)&GH2,  g_GH2);
    cudaGetSymbolAddress((void**)&dinv, g_dinv);
    cudaGetSymbolAddress((void**)&deg,  g_deg);
    cudaGetSymbolAddress((void**)&off,  g_off);
    cudaGetSymbolAddress((void**)&cur,  g_cur);
    cudaGetSymbolAddress((void**)&csr,  g_csr);
    cudaGetSymbolAddress((void**)&bsum, g_bsum);

    const int MB = (NN + 127) / 128;   // 782 row-blocks
    const int NB = (NN + 255) / 256;   // 391 scan blocks

    // degrees -> dinv, CSR build (reused by both conv layers)
    zero_deg_k<<<(NN + 255) / 256, 256>>>(deg);
    deg_k<<<(NE + 255) / 256, 256>>>(dst, deg);
    dinv_k<<<(NN + 255) / 256, 256>>>(deg, dinv);
    scan_part_k<<<NB, 256>>>(deg, bsum);
    scan_top_k<<<1, 512>>>(bsum, NB);
    scan_final_k<<<NB, 256>>>(deg, bsum, off, cur);
    fill_k<<<(NE + 255) / 256, 256>>>(src, dst, cur, csr);

    // preprocess MLP (tensor-core TF32, 3x compensated)
    { dim3 g(2, MB); tf32gemm_k<<<g, 256>>>(x,  W_p1, b_p1, H0, NN, 256, 256); }
    { dim3 g(1, MB); tf32gemm_k<<<g, 256>>>(H0, W_p2, b_p2, H1, NN, 128, 256); }

    // conv1: hw*dinv (HW1), then CSR gather (fused self-loop + bias + leaky)
    { dim3 g(1, MB); sgemm_k<128,64,16,8,4,2><<<g, 256>>>(H1, W_c1, nullptr, dinv, HW1, NN, 64, 128); }
    gather_k<64><<<(NN + 3) / 4, 256>>>(off, deg, csr, HW1, dinv, b_c1, C1);

    // GRU1 gates + gating + L2 normalize -> emb0 (second output, also conv2 input)
    { dim3 g(3, MB); sgemm_k<128,64,16,8,4,1><<<g, 256>>>(C1,    Wih1, bih1, nullptr, GI1, NN, 192, 64); }
    { dim3 g(3, MB); sgemm_k<128,64,16,8,4,1><<<g, 256>>>(prev0, Whh1, bhh1, nullptr, GH1, NN, 192, 64); }
    gate_k<64, true><<<NN / 2, 128>>>(GI1, GH1, prev0, emb0);

    // conv2
    { dim3 g(1, MB); sgemm_k<128,32,16,8,4,2><<<g, 128>>>(emb0, W_c2, nullptr, dinv, HW2, NN, 32, 64); }
    gather_k<32><<<(NN + 7) / 8, 256>>>(off, deg, csr, HW2, dinv, b_c2, C2);

    // GRU2 gates + gating -> h (first output)
    { dim3 g(3, MB); sgemm_k<128,32,16,8,4,1><<<g, 128>>>(C2,   Wih2, bih2, nullptr, GI2, NN, 96, 32); }
    { dim3 g(3, MB); sgemm_k<128,32,16,8,4,1><<<g, 128>>>(prev1, Whh2, bhh2, nullptr, GH2, NN, 96, 32); }
    gate_k<32, false><<<NN / 4, 128>>>(GI2, GH2, prev1, out);
}

// round 5
// speedup vs baseline: 1.6415x; 1.0136x over previous
#include <cuda_runtime.h>
#include <math.h>
#include <stdint.h>

#define NN 100000
#define NE 1600000

// ---------------- scratch (static device globals; no runtime allocation) ----
__device__ float g_H0  [(size_t)NN*256];
__device__ float g_H1  [(size_t)NN*128];
__device__ float g_HW1 [(size_t)NN*64];   // hw1 * dinv[row]
__device__ float g_C1  [(size_t)NN*64];   // conv1 activated output
__device__ float g_GI1 [(size_t)NN*192];
__device__ float g_GH1 [(size_t)NN*192];
__device__ float g_HW2 [(size_t)NN*32];   // hw2 * dinv[row]
__device__ float g_C2  [(size_t)NN*32];   // conv2 activated output
__device__ float g_GI2 [(size_t)NN*96];
__device__ float g_GH2 [(size_t)NN*96];
__device__ float g_dinv[NN];
__device__ int   g_deg [NN];
__device__ int   g_off [NN];
__device__ int   g_cur [NN];
__device__ int   g_csr [NE];
__device__ int   g_bsum[512];

__device__ __forceinline__ float leaky_f(float v) { return v > 0.f ? v : 0.01f * v; }
__device__ __forceinline__ float sigm_f(float x)  { return 1.f / (1.f + expf(-x)); }

__device__ __forceinline__ uint32_t f2tf32(float f) {
    uint32_t r;
    asm("cvt.rna.tf32.f32 %0, %1;" : "=r"(r) : "f"(f));
    return r;
}
__device__ __forceinline__ void mma_tf32(float c[4], const uint32_t a[4],
                                         uint32_t b0, uint32_t b1) {
    asm("mma.sync.aligned.m16n8k8.row.col.f32.tf32.tf32.f32 "
        "{%0,%1,%2,%3},{%4,%5,%6,%7},{%8,%9},{%0,%1,%2,%3};"
        : "+f"(c[0]), "+f"(c[1]), "+f"(c[2]), "+f"(c[3])
        : "r"(a[0]), "r"(a[1]), "r"(a[2]), "r"(a[3]), "r"(b0), "r"(b1));
}

// ---------------- TF32 tensor-core GEMM, BN=128 (3xTF32 compensated) ---------
// C[M,N] = leaky(A[M,K] @ B[K,N] + bias[col]).  BM=128, BN=128, BK=16.
// 256 threads = 8 warps (4 along M x 2 along N); warp tile 32x64.
__global__ void __launch_bounds__(256, 2)
tf32gemm_k(const float* __restrict__ A, const float* __restrict__ B,
           const float* __restrict__ bias, float* __restrict__ C,
           int M, int N, int K) {
    __shared__ float Ah[128][20], Al[128][20];     // pad 20: conflict-free frags
    __shared__ float Bh[16][136], Bl[16][136];     // pad 136 (mod 32 == 8)

    const int t    = threadIdx.x;
    const int lane = t & 31, wid = t >> 5;
    const int g    = lane >> 2, tg = lane & 3;
    const int wm   = (wid & 3) * 32;               // warp M offset in tile
    const int wn   = (wid >> 2) * 64;              // warp N offset in tile
    const int bx = blockIdx.x, by = blockIdx.y;

    float acc[2][8][4];
    #pragma unroll
    for (int i = 0; i < 2; i++)
        #pragma unroll
        for (int j = 0; j < 8; j++)
            #pragma unroll
            for (int q = 0; q < 4; q++) acc[i][j][q] = 0.f;

    for (int k0 = 0; k0 < K; k0 += 16) {
        __syncthreads();
        #pragma unroll
        for (int p = t; p < 512; p += 256) {
            int row = p >> 2, kc = (p & 3) * 4;
            int gr = by * 128 + row;
            float4 v = make_float4(0.f, 0.f, 0.f, 0.f);
            if (gr < M) v = *reinterpret_cast<const float4*>(A + (size_t)gr * K + k0 + kc);
            float4 h, l;
            h.x = __uint_as_float(f2tf32(v.x)); l.x = v.x - h.x;
            h.y = __uint_as_float(f2tf32(v.y)); l.y = v.y - h.y;
            h.z = __uint_as_float(f2tf32(v.z)); l.z = v.z - h.z;
            h.w = __uint_as_float(f2tf32(v.w)); l.w = v.w - h.w;
            *reinterpret_cast<float4*>(&Ah[row][kc]) = h;
            *reinterpret_cast<float4*>(&Al[row][kc]) = l;
        }
        #pragma unroll
        for (int p = t; p < 512; p += 256) {
            int krow = p >> 5, n = (p & 31) * 4;
            float4 v = *reinterpret_cast<const float4*>(
                B + (size_t)(k0 + krow) * N + bx * 128 + n);
            float4 h, l;
            h.x = __uint_as_float(f2tf32(v.x)); l.x = v.x - h.x;
            h.y = __uint_as_float(f2tf32(v.y)); l.y = v.y - h.y;
            h.z = __uint_as_float(f2tf32(v.z)); l.z = v.z - h.z;
            h.w = __uint_as_float(f2tf32(v.w)); l.w = v.w - h.w;
            *reinterpret_cast<float4*>(&Bh[krow][n]) = h;
            *reinterpret_cast<float4*>(&Bl[krow][n]) = l;
        }
        __syncthreads();

        #pragma unroll
        for (int s = 0; s < 16; s += 8) {
            uint32_t ah[2][4], al[2][4];
            #pragma unroll
            for (int i = 0; i < 2; i++) {
                int r0 = wm + i * 16 + g;
                ah[i][0] = __float_as_uint(Ah[r0    ][s + tg    ]);
                ah[i][1] = __float_as_uint(Ah[r0 + 8][s + tg    ]);
                ah[i][2] = __float_as_uint(Ah[r0    ][s + tg + 4]);
                ah[i][3] = __float_as_uint(Ah[r0 + 8][s + tg + 4]);
                al[i][0] = __float_as_uint(Al[r0    ][s + tg    ]);
                al[i][1] = __float_as_uint(Al[r0 + 8][s + tg    ]);
                al[i][2] = __float_as_uint(Al[r0    ][s + tg + 4]);
                al[i][3] = __float_as_uint(Al[r0 + 8][s + tg + 4]);
            }
            #pragma unroll
            for (int j = 0; j < 8; j++) {
                int cb = wn + j * 8 + g;
                uint32_t b0h = __float_as_uint(Bh[s + tg    ][cb]);
                uint32_t b1h = __float_as_uint(Bh[s + tg + 4][cb]);
                uint32_t b0l = __float_as_uint(Bl[s + tg    ][cb]);
                uint32_t b1l = __float_as_uint(Bl[s + tg + 4][cb]);
                #pragma unroll
                for (int i = 0; i < 2; i++) {
                    mma_tf32(acc[i][j], ah[i], b0h, b1h);   // hi*hi
                    mma_tf32(acc[i][j], al[i], b0h, b1h);   // lo*hi
                    mma_tf32(acc[i][j], ah[i], b0l, b1l);   // hi*lo
                }
            }
        }
    }

    #pragma unroll
    for (int i = 0; i < 2; i++) {
        int gr0 = by * 128 + wm + i * 16 + g;
        #pragma unroll
        for (int j = 0; j < 8; j++) {
            int gc = bx * 128 + wn + j * 8 + 2 * tg;
            float b0 = bias[gc], b1 = bias[gc + 1];
            if (gr0 < M) {
                float2 v = make_float2(leaky_f(acc[i][j][0] + b0),
                                       leaky_f(acc[i][j][1] + b1));
                *reinterpret_cast<float2*>(C + (size_t)gr0 * N + gc) = v;
            }
            if (gr0 + 8 < M) {
                float2 v = make_float2(leaky_f(acc[i][j][2] + b0),
                                       leaky_f(acc[i][j][3] + b1));
                *reinterpret_cast<float2*>(C + (size_t)(gr0 + 8) * N + gc) = v;
            }
        }
    }
}

// ---------------- TF32 tensor-core GEMM, BN=64 (small-N layers) --------------
// MODE 1: C = acc + bias[col];  MODE 2: C = acc * dinv[row]
// BM=128, BN=64, BK=16. 8 warps (4 along M x 2 along N); warp tile 32x32.
// N need not be a multiple of 64 (guards + zero-fill); K multiple of 16.
template<int MODE>
__global__ void __launch_bounds__(256, 2)
tf32gemm64_k(const float* __restrict__ A, const float* __restrict__ B,
             const float* __restrict__ bias, const float* __restrict__ dinv,
             float* __restrict__ C, int M, int N, int K) {
    __shared__ float Ah[128][20], Al[128][20];
    __shared__ float Bh[16][72], Bl[16][72];       // 72 mod 32 == 8: conflict-free

    const int t    = threadIdx.x;
    const int lane = t & 31, wid = t >> 5;
    const int g    = lane >> 2, tg = lane & 3;
    const int wm   = (wid & 3) * 32;
    const int wn   = (wid >> 2) * 32;
    const int bx = blockIdx.x, by = blockIdx.y;

    float acc[2][4][4];
    #pragma unroll
    for (int i = 0; i < 2; i++)
        #pragma unroll
        for (int j = 0; j < 4; j++)
            #pragma unroll
            for (int q = 0; q < 4; q++) acc[i][j][q] = 0.f;

    for (int k0 = 0; k0 < K; k0 += 16) {
        __syncthreads();
        // stage A (128x16): 512 float4, 2 per thread
        #pragma unroll
        for (int p = t; p < 512; p += 256) {
            int row = p >> 2, kc = (p & 3) * 4;
            int gr = by * 128 + row;
            float4 v = make_float4(0.f, 0.f, 0.f, 0.f);
            if (gr < M) v = *reinterpret_cast<const float4*>(A + (size_t)gr * K + k0 + kc);
            float4 h, l;
            h.x = __uint_as_float(f2tf32(v.x)); l.x = v.x - h.x;
            h.y = __uint_as_float(f2tf32(v.y)); l.y = v.y - h.y;
            h.z = __uint_as_float(f2tf32(v.z)); l.z = v.z - h.z;
            h.w = __uint_as_float(f2tf32(v.w)); l.w = v.w - h.w;
            *reinterpret_cast<float4*>(&Ah[row][kc]) = h;
            *reinterpret_cast<float4*>(&Al[row][kc]) = l;
        }
        // stage B (16x64): 256 float4, 1 per thread; zero-fill cols >= N
        {
            int krow = t >> 4, n = (t & 15) * 4;
            int gc = bx * 64 + n;
            float4 v = make_float4(0.f, 0.f, 0.f, 0.f);
            if (gc + 3 < N)
                v = *reinterpret_cast<const float4*>(B + (size_t)(k0 + krow) * N + gc);
            float4 h, l;
            h.x = __uint_as_float(f2tf32(v.x)); l.x = v.x - h.x;
            h.y = __uint_as_float(f2tf32(v.y)); l.y = v.y - h.y;
            h.z = __uint_as_float(f2tf32(v.z)); l.z = v.z - h.z;
            h.w = __uint_as_float(f2tf32(v.w)); l.w = v.w - h.w;
            *reinterpret_cast<float4*>(&Bh[krow][n]) = h;
            *reinterpret_cast<float4*>(&Bl[krow][n]) = l;
        }
        __syncthreads();

        #pragma unroll
        for (int s = 0; s < 16; s += 8) {
            uint32_t ah[2][4], al[2][4];
            #pragma unroll
            for (int i = 0; i < 2; i++) {
                int r0 = wm + i * 16 + g;
                ah[i][0] = __float_as_uint(Ah[r0    ][s + tg    ]);
                ah[i][1] = __float_as_uint(Ah[r0 + 8][s + tg    ]);
                ah[i][2] = __float_as_uint(Ah[r0    ][s + tg + 4]);
                ah[i][3] = __float_as_uint(Ah[r0 + 8][s + tg + 4]);
                al[i][0] = __float_as_uint(Al[r0    ][s + tg    ]);
                al[i][1] = __float_as_uint(Al[r0 + 8][s + tg    ]);
                al[i][2] = __float_as_uint(Al[r0    ][s + tg + 4]);
                al[i][3] = __float_as_uint(Al[r0 + 8][s + tg + 4]);
            }
            #pragma unroll
            for (int j = 0; j < 4; j++) {
                int cb = wn + j * 8 + g;
                uint32_t b0h = __float_as_uint(Bh[s + tg    ][cb]);
                uint32_t b1h = __float_as_uint(Bh[s + tg + 4][cb]);
                uint32_t b0l = __float_as_uint(Bl[s + tg    ][cb]);
                uint32_t b1l = __float_as_uint(Bl[s + tg + 4][cb]);
                #pragma unroll
                for (int i = 0; i < 2; i++) {
                    mma_tf32(acc[i][j], ah[i], b0h, b1h);
                    mma_tf32(acc[i][j], al[i], b0h, b1h);
                    mma_tf32(acc[i][j], ah[i], b0l, b1l);
                }
            }
        }
    }

    #pragma unroll
    for (int i = 0; i < 2; i++) {
        int gr0 = by * 128 + wm + i * 16 + g;
        float d0 = (MODE == 2 && gr0     < M) ? dinv[gr0]     : 0.f;
        float d1 = (MODE == 2 && gr0 + 8 < M) ? dinv[gr0 + 8] : 0.f;
        #pragma unroll
        for (int j = 0; j < 4; j++) {
            int gc = bx * 64 + wn + j * 8 + 2 * tg;
            if (gc + 1 >= N && gc >= N) continue;
            float b0 = 0.f, b1 = 0.f;
            if (MODE == 1) { b0 = bias[gc]; b1 = bias[gc + 1]; }
            if (gr0 < M) {
                float v0 = (MODE == 1) ? acc[i][j][0] + b0 : acc[i][j][0] * d0;
                float v1 = (MODE == 1) ? acc[i][j][1] + b1 : acc[i][j][1] * d0;
                *reinterpret_cast<float2*>(C + (size_t)gr0 * N + gc) = make_float2(v0, v1);
            }
            if (gr0 + 8 < M) {
                float v0 = (MODE == 1) ? acc[i][j][2] + b0 : acc[i][j][2] * d1;
                float v1 = (MODE == 1) ? acc[i][j][3] + b1 : acc[i][j][3] * d1;
                *reinterpret_cast<float2*>(C + (size_t)(gr0 + 8) * N + gc) = make_float2(v0, v1);
            }
        }
    }
}

// ---------------- degree / dinv ---------------------------------------------
__global__ void zero_deg_k(int* deg) {
    int i = blockIdx.x * blockDim.x + threadIdx.x;
    if (i < NN) deg[i] = 0;
}
__global__ void deg_k(const int* __restrict__ dst, int* __restrict__ deg) {
    int e = blockIdx.x * blockDim.x + threadIdx.x;
    if (e < NE) atomicAdd(&deg[dst[e]], 1);
}
__global__ void dinv_k(const int* __restrict__ deg, float* __restrict__ dinv) {
    int i = blockIdx.x * blockDim.x + threadIdx.x;
    if (i < NN) dinv[i] = rsqrtf((float)deg[i] + 1.0f);
}

// ---------------- parallel CSR prefix sum (3 kernels) ------------------------
__global__ void scan_part_k(const int* __restrict__ deg, int* __restrict__ bsum) {
    __shared__ int s[256];
    int t = threadIdx.x;
    int i = blockIdx.x * 256 + t;
    s[t] = (i < NN) ? deg[i] : 0;
    __syncthreads();
    for (int o = 128; o > 0; o >>= 1) {
        if (t < o) s[t] += s[t + o];
        __syncthreads();
    }
    if (t == 0) bsum[blockIdx.x] = s[0];
}
__global__ void scan_top_k(int* __restrict__ bsum, int nb) {
    __shared__ int s[512];
    int t = threadIdx.x;
    int v = (t < nb) ? bsum[t] : 0;
    s[t] = v;
    __syncthreads();
    for (int o = 1; o < 512; o <<= 1) {
        int u = (t >= o) ? s[t - o] : 0;
        __syncthreads();
        s[t] += u;
        __syncthreads();
    }
    if (t < nb) bsum[t] = s[t] - v;   // exclusive
}
__global__ void scan_final_k(const int* __restrict__ deg, const int* __restrict__ bsum,
                             int* __restrict__ off, int* __restrict__ cur) {
    __shared__ int s[256];
    int t = threadIdx.x;
    int i = blockIdx.x * 256 + t;
    int d = (i < NN) ? deg[i] : 0;
    s[t] = d;
    __syncthreads();
    for (int o = 1; o < 256; o <<= 1) {
        int u = (t >= o) ? s[t - o] : 0;
        __syncthreads();
        s[t] += u;
        __syncthreads();
    }
    if (i < NN) {
        int o_ = bsum[blockIdx.x] + s[t] - d;
        off[i] = o_;
        cur[i] = o_;
    }
}

__global__ void fill_k(const int* __restrict__ src, const int* __restrict__ dst,
                       int* __restrict__ cur, int* __restrict__ csr) {
    int e = blockIdx.x * blockDim.x + threadIdx.x;
    if (e < NE) {
        int pos = atomicAdd(&cur[dst[e]], 1);
        csr[pos] = src[e];
    }
}

// ---------------- CSR gather: fused conv agg + self-loop + bias + leaky -----
template<int F>
__global__ void gather_k(const int* __restrict__ off, const int* __restrict__ deg,
                         const int* __restrict__ csr, const float* __restrict__ HWd,
                         const float* __restrict__ dinv, const float* __restrict__ bias,
                         float* __restrict__ Out) {
    constexpr int NPB = 256 / F;
    int tid = threadIdx.x;
    int ln = tid / F, f = tid % F;
    int n = blockIdx.x * NPB + ln;
    if (n >= NN) return;

    int s0 = off[n], cnt = deg[n];
    float a0 = 0.f, a1 = 0.f, a2 = 0.f, a3 = 0.f;
    int i = 0;
    for (; i + 4 <= cnt; i += 4) {
        int e0 = csr[s0 + i], e1 = csr[s0 + i + 1];
        int e2 = csr[s0 + i + 2], e3 = csr[s0 + i + 3];
        a0 += HWd[(size_t)e0 * F + f];
        a1 += HWd[(size_t)e1 * F + f];
        a2 += HWd[(size_t)e2 * F + f];
        a3 += HWd[(size_t)e3 * F + f];
    }
    for (; i < cnt; i++) a0 += HWd[(size_t)csr[s0 + i] * F + f];

    float sum = (a0 + a1) + (a2 + a3);
    float v = dinv[n] * (sum + HWd[(size_t)n * F + f]) + bias[f];
    Out[(size_t)n * F + f] = leaky_f(v);
}

// ---------------- GRU gating (+ optional row L2 normalize) ------------------
template<int H, bool NORM>
__global__ void gate_k(const float* __restrict__ GI, const float* __restrict__ GH,
                       const float* __restrict__ Hp, float* __restrict__ Out) {
    constexpr int NPB = 128 / H;
    __shared__ float sred[8];
    int tid = threadIdx.x;
    int ln = tid / H, j = tid % H;
    int node = blockIdx.x * NPB + ln;
    if (node >= NN) return;

    size_t g = (size_t)node * 3 * H + j;
    float r  = sigm_f(GI[g] + GH[g]);
    float z  = sigm_f(GI[g + H] + GH[g + H]);
    float nc = tanhf(GI[g + 2 * H] + r * GH[g + 2 * H]);
    float hp = Hp[(size_t)node * H + j];
    float h  = (1.f - z) * nc + z * hp;

    if constexpr (NORM) {
        float sq = h * h;
        #pragma unroll
        for (int o = 16; o > 0; o >>= 1) sq += __shfl_xor_sync(0xffffffffu, sq, o);
        int warp = tid >> 5;
        if ((tid & 31) == 0) sred[warp] = sq;
        __syncthreads();
        float tot = sred[ln * 2] + sred[ln * 2 + 1];
        h *= rsqrtf(tot);
    }
    Out[(size_t)node * H + j] = h;
}

// ---------------- launcher ---------------------------------------------------
extern "C" void kernel_launch(void* const* d_in, const int* in_sizes, int n_in,
                              void* d_out, int out_size) {
    const float* x     = (const float*)d_in[0];
    const float* prev0 = (const float*)d_in[1];
    const float* prev1 = (const float*)d_in[2];
    const float* W_p1  = (const float*)d_in[3];
    const float* b_p1  = (const float*)d_in[4];
    const float* W_p2  = (const float*)d_in[5];
    const float* b_p2  = (const float*)d_in[6];
    const float* W_c1  = (const float*)d_in[7];
    const float* b_c1  = (const float*)d_in[8];
    const float* W_c2  = (const float*)d_in[9];
    const float* b_c2  = (const float*)d_in[10];
    const float* Wih1  = (const float*)d_in[11];
    const float* Whh1  = (const float*)d_in[12];
    const float* bih1  = (const float*)d_in[13];
    const float* bhh1  = (const float*)d_in[14];
    const float* Wih2  = (const float*)d_in[15];
    const float* Whh2  = (const float*)d_in[16];
    const float* bih2  = (const float*)d_in[17];
    const float* bhh2  = (const float*)d_in[18];
    const int*   src   = (const int*)d_in[19];
    const int*   dst   = (const int*)d_in[20];

    float* out  = (float*)d_out;
    float* emb0 = out + (size_t)NN * 32;   // output tuple (h[N,32], emb0[N,64]) flattened

    float *H0, *H1, *HW1, *C1, *GI1, *GH1, *HW2, *C2, *GI2, *GH2, *dinv;
    int *deg, *off, *cur, *csr, *bsum;
    cudaGetSymbolAddress((void**)&H0,   g_H0);
    cudaGetSymbolAddress((void**)&H1,   g_H1);
    cudaGetSymbolAddress((void**)&HW1,  g_HW1);
    cudaGetSymbolAddress((void**)&C1,   g_C1);
    cudaGetSymbolAddress((void**)&GI1,  g_GI1);
    cudaGetSymbolAddress((void**)&GH1,  g_GH1);
    cudaGetSymbolAddress((void**)&HW2,  g_HW2);
    cudaGetSymbolAddress((void**)&C2,   g_C2);
    cudaGetSymbolAddress((void**)&GI2,  g_GI2);
    cudaGetSymbolAddress((void**)&GH2,  g_GH2);
    cudaGetSymbolAddress((void**)&dinv, g_dinv);
    cudaGetSymbolAddress((void**)&deg,  g_deg);
    cudaGetSymbolAddress((void**)&off,  g_off);
    cudaGetSymbolAddress((void**)&cur,  g_cur);
    cudaGetSymbolAddress((void**)&csr,  g_csr);
    cudaGetSymbolAddress((void**)&bsum, g_bsum);

    const int MB = (NN + 127) / 128;   // 782 row-blocks
    const int NB = (NN + 255) / 256;   // 391 scan blocks

    // degrees -> dinv, CSR build (reused by both conv layers)
    zero_deg_k<<<(NN + 255) / 256, 256>>>(deg);
    deg_k<<<(NE + 255) / 256, 256>>>(dst, deg);
    dinv_k<<<(NN + 255) / 256, 256>>>(deg, dinv);
    scan_part_k<<<NB, 256>>>(deg, bsum);
    scan_top_k<<<1, 512>>>(bsum, NB);
    scan_final_k<<<NB, 256>>>(deg, bsum, off, cur);
    fill_k<<<(NE + 255) / 256, 256>>>(src, dst, cur, csr);

    // preprocess MLP (tensor-core TF32, 3x compensated)
    { dim3 g(2, MB); tf32gemm_k<<<g, 256>>>(x,  W_p1, b_p1, H0, NN, 256, 256); }
    { dim3 g(1, MB); tf32gemm_k<<<g, 256>>>(H0, W_p2, b_p2, H1, NN, 128, 256); }

    // conv1: hw*dinv (HW1), then CSR gather (fused self-loop + bias + leaky)
    { dim3 g(1, MB); tf32gemm64_k<2><<<g, 256>>>(H1, W_c1, nullptr, dinv, HW1, NN, 64, 128); }
    gather_k<64><<<(NN + 3) / 4, 256>>>(off, deg, csr, HW1, dinv, b_c1, C1);

    // GRU1 gates + gating + L2 normalize -> emb0 (second output, also conv2 input)
    { dim3 g(3, MB); tf32gemm64_k<1><<<g, 256>>>(C1,    Wih1, bih1, nullptr, GI1, NN, 192, 64); }
    { dim3 g(3, MB); tf32gemm64_k<1><<<g, 256>>>(prev0, Whh1, bhh1, nullptr, GH1, NN, 192, 64); }
    gate_k<64, true><<<NN / 2, 128>>>(GI1, GH1, prev0, emb0);

    // conv2
    { dim3 g(1, MB); tf32gemm64_k<2><<<g, 256>>>(emb0, W_c2, nullptr, dinv, HW2, NN, 32, 64); }
    gather_k<32><<<(NN + 7) / 8, 256>>>(off, deg, csr, HW2, dinv, b_c2, C2);

    // GRU2 gates + gating -> h (first output)
    { dim3 g(2, MB); tf32gemm64_k<1><<<g, 256>>>(C2,    Wih2, bih2, nullptr, GI2, NN, 96, 32); }
    { dim3 g(2, MB); tf32gemm64_k<1><<<g, 256>>>(prev1, Whh2, bhh2, nullptr, GH2, NN, 96, 32); }
    gate_k<32, false><<<NN / 4, 128>>>(GI2, GH2, prev1, out);
}

// round 6
// speedup vs baseline: 2.1580x; 1.3147x over previous
#include <cuda_runtime.h>
#include <cuda_bf16.h>
#include <math.h>
#include <stdint.h>

#define NN 100000
#define NE 1600000

// ---------------- scratch (static device globals; no runtime allocation) ----
__device__ float g_H0  [(size_t)NN*256];
__device__ float g_H1  [(size_t)NN*128];
__device__ float g_HW1 [(size_t)NN*64];
__device__ float g_C1  [(size_t)NN*64];
__device__ float g_GI1 [(size_t)NN*192];
__device__ float g_GH1 [(size_t)NN*192];
__device__ float g_HW2 [(size_t)NN*32];
__device__ float g_C2  [(size_t)NN*32];
__device__ float g_GI2 [(size_t)NN*96];
__device__ float g_GH2 [(size_t)NN*96];
__device__ float g_dinv[NN];
__device__ int   g_deg [NN];
__device__ int   g_off [NN];
__device__ int   g_cur [NN];
__device__ int   g_csr [NE];
__device__ int   g_bsum[512];

__device__ __forceinline__ float leaky_f(float v) { return v > 0.f ? v : 0.01f * v; }
__device__ __forceinline__ float sigm_f(float x)  { return 1.f / (1.f + expf(-x)); }

// pack two f32 -> bf16x2; 'e' (even-k) goes to the LOW half, 'o' to the HIGH half
__device__ __forceinline__ uint32_t packbf(float e, float o) {
    uint32_t r;
    asm("cvt.rn.bf16x2.f32 %0, %1, %2;" : "=r"(r) : "f"(o), "f"(e));
    return r;
}
__device__ __forceinline__ float bf_hi(float a) {
    return __bfloat162float(__float2bfloat16(a));
}
__device__ __forceinline__ void mma_bf16(float c[4], const uint32_t a[4],
                                         uint32_t b0, uint32_t b1) {
    asm("mma.sync.aligned.m16n8k16.row.col.f32.bf16.bf16.f32 "
        "{%0,%1,%2,%3},{%4,%5,%6,%7},{%8,%9},{%0,%1,%2,%3};"
        : "+f"(c[0]), "+f"(c[1]), "+f"(c[2]), "+f"(c[3])
        : "r"(a[0]), "r"(a[1]), "r"(a[2]), "r"(a[3]), "r"(b0), "r"(b1));
}

// ---------------- BF16x3 tensor-core GEMM, BN=128 ----------------------------
// C[M,N] = leaky(A[M,K] @ B[K,N] + bias[col]).  BM=128, BN=128, BK=16.
// 256 threads = 8 warps (4xM, 2xN); warp tile 32x64. K multiple of 16.
// Packed layout: X2[row][kk] = bf16x2 of k=2kk (low) and k=2kk+1 (high).
__global__ void __launch_bounds__(256, 2)
bf16gemm_k(const float* __restrict__ A, const float* __restrict__ B,
           const float* __restrict__ bias, float* __restrict__ C,
           int M, int N, int K) {
    __shared__ uint32_t A2h[128][12], A2l[128][12];   // cols 0..7 used; stride 12 conflict-free
    __shared__ uint32_t B2h[8][136],  B2l[8][136];    // cols 0..127 used; 136 mod 32 == 8

    const int t    = threadIdx.x;
    const int lane = t & 31, wid = t >> 5;
    const int g    = lane >> 2, tg = lane & 3;
    const int wm   = (wid & 3) * 32;
    const int wn   = (wid >> 2) * 64;
    const int bx = blockIdx.x, by = blockIdx.y;

    float acc[2][8][4];
    #pragma unroll
    for (int i = 0; i < 2; i++)
        #pragma unroll
        for (int j = 0; j < 8; j++)
            #pragma unroll
            for (int q = 0; q < 4; q++) acc[i][j][q] = 0.f;

    for (int k0 = 0; k0 < K; k0 += 16) {
        __syncthreads();
        // stage A (128x16): 512 float4 units, 2 per thread
        #pragma unroll
        for (int p = t; p < 512; p += 256) {
            int row = p >> 2, kc = (p & 3) * 4, kk = (p & 3) * 2;
            int gr = by * 128 + row;
            float4 v = make_float4(0.f, 0.f, 0.f, 0.f);
            if (gr < M) v = *reinterpret_cast<const float4*>(A + (size_t)gr * K + k0 + kc);
            float hx = bf_hi(v.x), hy = bf_hi(v.y), hz = bf_hi(v.z), hw = bf_hi(v.w);
            A2h[row][kk    ] = packbf(v.x, v.y);
            A2h[row][kk + 1] = packbf(v.z, v.w);
            A2l[row][kk    ] = packbf(v.x - hx, v.y - hy);
            A2l[row][kk + 1] = packbf(v.z - hz, v.w - hw);
        }
        // stage B (16x128): 256 (kpair, 4n) units, 1 per thread
        {
            int kk = t >> 5, n4 = (t & 31) * 4;
            const float* bp = B + (size_t)(k0 + 2 * kk) * N + bx * 128 + n4;
            float4 u = *reinterpret_cast<const float4*>(bp);       // k = 2kk
            float4 w = *reinterpret_cast<const float4*>(bp + N);   // k = 2kk+1
            float hux = bf_hi(u.x), huy = bf_hi(u.y), huz = bf_hi(u.z), huw = bf_hi(u.w);
            float hwx = bf_hi(w.x), hwy = bf_hi(w.y), hwz = bf_hi(w.z), hww = bf_hi(w.w);
            B2h[kk][n4 + 0] = packbf(u.x, w.x);
            B2h[kk][n4 + 1] = packbf(u.y, w.y);
            B2h[kk][n4 + 2] = packbf(u.z, w.z);
            B2h[kk][n4 + 3] = packbf(u.w, w.w);
            B2l[kk][n4 + 0] = packbf(u.x - hux, w.x - hwx);
            B2l[kk][n4 + 1] = packbf(u.y - huy, w.y - hwy);
            B2l[kk][n4 + 2] = packbf(u.z - huz, w.z - hwz);
            B2l[kk][n4 + 3] = packbf(u.w - huw, w.w - hww);
        }
        __syncthreads();

        uint32_t ah[2][4], al[2][4];
        #pragma unroll
        for (int i = 0; i < 2; i++) {
            int r0 = wm + i * 16 + g;
            ah[i][0] = A2h[r0    ][tg    ]; ah[i][1] = A2h[r0 + 8][tg    ];
            ah[i][2] = A2h[r0    ][tg + 4]; ah[i][3] = A2h[r0 + 8][tg + 4];
            al[i][0] = A2l[r0    ][tg    ]; al[i][1] = A2l[r0 + 8][tg    ];
            al[i][2] = A2l[r0    ][tg + 4]; al[i][3] = A2l[r0 + 8][tg + 4];
        }
        #pragma unroll
        for (int j = 0; j < 8; j++) {
            int cb = wn + j * 8 + g;
            uint32_t bh0 = B2h[tg][cb], bh1 = B2h[tg + 4][cb];
            uint32_t bl0 = B2l[tg][cb], bl1 = B2l[tg + 4][cb];
            #pragma unroll
            for (int i = 0; i < 2; i++) {
                mma_bf16(acc[i][j], ah[i], bh0, bh1);   // hi*hi
                mma_bf16(acc[i][j], al[i], bh0, bh1);   // lo*hi
                mma_bf16(acc[i][j], ah[i], bl0, bl1);   // hi*lo
            }
        }
    }

    #pragma unroll
    for (int i = 0; i < 2; i++) {
        int gr0 = by * 128 + wm + i * 16 + g;
        #pragma unroll
        for (int j = 0; j < 8; j++) {
            int gc = bx * 128 + wn + j * 8 + 2 * tg;
            float b0 = bias[gc], b1 = bias[gc + 1];
            if (gr0 < M) {
                float2 v = make_float2(leaky_f(acc[i][j][0] + b0),
                                       leaky_f(acc[i][j][1] + b1));
                *reinterpret_cast<float2*>(C + (size_t)gr0 * N + gc) = v;
            }
            if (gr0 + 8 < M) {
                float2 v = make_float2(leaky_f(acc[i][j][2] + b0),
                                       leaky_f(acc[i][j][3] + b1));
                *reinterpret_cast<float2*>(C + (size_t)(gr0 + 8) * N + gc) = v;
            }
        }
    }
}

// ---------------- BF16x3 tensor-core GEMM, BN=64 (small-N layers) ------------
// MODE 1: C = acc + bias[col];  MODE 2: C = acc * dinv[row]
template<int MODE>
__global__ void __launch_bounds__(256, 2)
bf16gemm64_k(const float* __restrict__ A, const float* __restrict__ B,
             const float* __restrict__ bias, const float* __restrict__ dinv,
             float* __restrict__ C, int M, int N, int K) {
    __shared__ uint32_t A2h[128][12], A2l[128][12];
    __shared__ uint32_t B2h[8][72],  B2l[8][72];      // 72 mod 32 == 8: conflict-free

    const int t    = threadIdx.x;
    const int lane = t & 31, wid = t >> 5;
    const int g    = lane >> 2, tg = lane & 3;
    const int wm   = (wid & 3) * 32;
    const int wn   = (wid >> 2) * 32;
    const int bx = blockIdx.x, by = blockIdx.y;

    float acc[2][4][4];
    #pragma unroll
    for (int i = 0; i < 2; i++)
        #pragma unroll
        for (int j = 0; j < 4; j++)
            #pragma unroll
            for (int q = 0; q < 4; q++) acc[i][j][q] = 0.f;

    for (int k0 = 0; k0 < K; k0 += 16) {
        __syncthreads();
        #pragma unroll
        for (int p = t; p < 512; p += 256) {
            int row = p >> 2, kc = (p & 3) * 4, kk = (p & 3) * 2;
            int gr = by * 128 + row;
            float4 v = make_float4(0.f, 0.f, 0.f, 0.f);
            if (gr < M) v = *reinterpret_cast<const float4*>(A + (size_t)gr * K + k0 + kc);
            float hx = bf_hi(v.x), hy = bf_hi(v.y), hz = bf_hi(v.z), hw = bf_hi(v.w);
            A2h[row][kk    ] = packbf(v.x, v.y);
            A2h[row][kk + 1] = packbf(v.z, v.w);
            A2l[row][kk    ] = packbf(v.x - hx, v.y - hy);
            A2l[row][kk + 1] = packbf(v.z - hz, v.w - hw);
        }
        // stage B (16x64): 128 (kpair, 4n) units on threads t<128; zero-fill cols >= N
        if (t < 128) {
            int kk = t >> 4, n4 = (t & 15) * 4;
            int gc = bx * 64 + n4;
            float4 u = make_float4(0.f, 0.f, 0.f, 0.f);
            float4 w = make_float4(0.f, 0.f, 0.f, 0.f);
            if (gc + 3 < N) {
                const float* bp = B + (size_t)(k0 + 2 * kk) * N + gc;
                u = *reinterpret_cast<const float4*>(bp);
                w = *reinterpret_cast<const float4*>(bp + N);
            }
            float hux = bf_hi(u.x), huy = bf_hi(u.y), huz = bf_hi(u.z), huw = bf_hi(u.w);
            float hwx = bf_hi(w.x), hwy = bf_hi(w.y), hwz = bf_hi(w.z), hww = bf_hi(w.w);
            B2h[kk][n4 + 0] = packbf(u.x, w.x);
            B2h[kk][n4 + 1] = packbf(u.y, w.y);
            B2h[kk][n4 + 2] = packbf(u.z, w.z);
            B2h[kk][n4 + 3] = packbf(u.w, w.w);
            B2l[kk][n4 + 0] = packbf(u.x - hux, w.x - hwx);
            B2l[kk][n4 + 1] = packbf(u.y - huy, w.y - hwy);
            B2l[kk][n4 + 2] = packbf(u.z - huz, w.z - hwz);
            B2l[kk][n4 + 3] = packbf(u.w - huw, w.w - hww);
        }
        __syncthreads();

        uint32_t ah[2][4], al[2][4];
        #pragma unroll
        for (int i = 0; i < 2; i++) {
            int r0 = wm + i * 16 + g;
            ah[i][0] = A2h[r0    ][tg    ]; ah[i][1] = A2h[r0 + 8][tg    ];
            ah[i][2] = A2h[r0    ][tg + 4]; ah[i][3] = A2h[r0 + 8][tg + 4];
            al[i][0] = A2l[r0    ][tg    ]; al[i][1] = A2l[r0 + 8][tg    ];
            al[i][2] = A2l[r0    ][tg + 4]; al[i][3] = A2l[r0 + 8][tg + 4];
        }
        #pragma unroll
        for (int j = 0; j < 4; j++) {
            int cb = wn + j * 8 + g;
            uint32_t bh0 = B2h[tg][cb], bh1 = B2h[tg + 4][cb];
            uint32_t bl0 = B2l[tg][cb], bl1 = B2l[tg + 4][cb];
            #pragma unroll
            for (int i = 0; i < 2; i++) {
                mma_bf16(acc[i][j], ah[i], bh0, bh1);
                mma_bf16(acc[i][j], al[i], bh0, bh1);
                mma_bf16(acc[i][j], ah[i], bl0, bl1);
            }
        }
    }

    #pragma unroll
    for (int i = 0; i < 2; i++) {
        int gr0 = by * 128 + wm + i * 16 + g;
        float d0 = (MODE == 2 && gr0     < M) ? dinv[gr0]     : 0.f;
        float d1 = (MODE == 2 && gr0 + 8 < M) ? dinv[gr0 + 8] : 0.f;
        #pragma unroll
        for (int j = 0; j < 4; j++) {
            int gc = bx * 64 + wn + j * 8 + 2 * tg;
            if (gc >= N) continue;
            float b0 = 0.f, b1 = 0.f;
            if (MODE == 1) { b0 = bias[gc]; b1 = bias[gc + 1]; }
            if (gr0 < M) {
                float v0 = (MODE == 1) ? acc[i][j][0] + b0 : acc[i][j][0] * d0;
                float v1 = (MODE == 1) ? acc[i][j][1] + b1 : acc[i][j][1] * d0;
                *reinterpret_cast<float2*>(C + (size_t)gr0 * N + gc) = make_float2(v0, v1);
            }
            if (gr0 + 8 < M) {
                float v0 = (MODE == 1) ? acc[i][j][2] + b0 : acc[i][j][2] * d1;
                float v1 = (MODE == 1) ? acc[i][j][3] + b1 : acc[i][j][3] * d1;
                *reinterpret_cast<float2*>(C + (size_t)(gr0 + 8) * N + gc) = make_float2(v0, v1);
            }
        }
    }
}

// ---------------- degree / dinv ---------------------------------------------
__global__ void zero_deg_k(int* deg) {
    int i = blockIdx.x * blockDim.x + threadIdx.x;
    if (i < NN) deg[i] = 0;
}
__global__ void deg_k(const int* __restrict__ dst, int* __restrict__ deg) {
    int e = blockIdx.x * blockDim.x + threadIdx.x;
    if (e < NE) atomicAdd(&deg[dst[e]], 1);
}
__global__ void dinv_k(const int* __restrict__ deg, float* __restrict__ dinv) {
    int i = blockIdx.x * blockDim.x + threadIdx.x;
    if (i < NN) dinv[i] = rsqrtf((float)deg[i] + 1.0f);
}

// ---------------- parallel CSR prefix sum (3 kernels) ------------------------
__global__ void scan_part_k(const int* __restrict__ deg, int* __restrict__ bsum) {
    __shared__ int s[256];
    int t = threadIdx.x;
    int i = blockIdx.x * 256 + t;
    s[t] = (i < NN) ? deg[i] : 0;
    __syncthreads();
    for (int o = 128; o > 0; o >>= 1) {
        if (t < o) s[t] += s[t + o];
        __syncthreads();
    }
    if (t == 0) bsum[blockIdx.x] = s[0];
}
__global__ void scan_top_k(int* __restrict__ bsum, int nb) {
    __shared__ int s[512];
    int t = threadIdx.x;
    int v = (t < nb) ? bsum[t] : 0;
    s[t] = v;
    __syncthreads();
    for (int o = 1; o < 512; o <<= 1) {
        int u = (t >= o) ? s[t - o] : 0;
        __syncthreads();
        s[t] += u;
        __syncthreads();
    }
    if (t < nb) bsum[t] = s[t] - v;   // exclusive
}
__global__ void scan_final_k(const int* __restrict__ deg, const int* __restrict__ bsum,
                             int* __restrict__ off, int* __restrict__ cur) {
    __shared__ int s[256];
    int t = threadIdx.x;
    int i = blockIdx.x * 256 + t;
    int d = (i < NN) ? deg[i] : 0;
    s[t] = d;
    __syncthreads();
    for (int o = 1; o < 256; o <<= 1) {
        int u = (t >= o) ? s[t - o] : 0;
        __syncthreads();
        s[t] += u;
        __syncthreads();
    }
    if (i < NN) {
        int o_ = bsum[blockIdx.x] + s[t] - d;
        off[i] = o_;
        cur[i] = o_;
    }
}

__global__ void fill_k(const int* __restrict__ src, const int* __restrict__ dst,
                       int* __restrict__ cur, int* __restrict__ csr) {
    int e = blockIdx.x * blockDim.x + threadIdx.x;
    if (e < NE) {
        int pos = atomicAdd(&cur[dst[e]], 1);
        csr[pos] = src[e];
    }
}

// ---------------- CSR gather: fused conv agg + self-loop + bias + leaky -----
template<int F>
__global__ void gather_k(const int* __restrict__ off, const int* __restrict__ deg,
                         const int* __restrict__ csr, const float* __restrict__ HWd,
                         const float* __restrict__ dinv, const float* __restrict__ bias,
                         float* __restrict__ Out) {
    constexpr int NPB = 256 / F;
    int tid = threadIdx.x;
    int ln = tid / F, f = tid % F;
    int n = blockIdx.x * NPB + ln;
    if (n >= NN) return;

    int s0 = off[n], cnt = deg[n];
    float a0 = 0.f, a1 = 0.f, a2 = 0.f, a3 = 0.f;
    int i = 0;
    for (; i + 4 <= cnt; i += 4) {
        int e0 = csr[s0 + i], e1 = csr[s0 + i + 1];
        int e2 = csr[s0 + i + 2], e3 = csr[s0 + i + 3];
        a0 += HWd[(size_t)e0 * F + f];
        a1 += HWd[(size_t)e1 * F + f];
        a2 += HWd[(size_t)e2 * F + f];
        a3 += HWd[(size_t)e3 * F + f];
    }
    for (; i < cnt; i++) a0 += HWd[(size_t)csr[s0 + i] * F + f];

    float sum = (a0 + a1) + (a2 + a3);
    float v = dinv[n] * (sum + HWd[(size_t)n * F + f]) + bias[f];
    Out[(size_t)n * F + f] = leaky_f(v);
}

// ---------------- GRU gating (+ optional row L2 normalize) ------------------
template<int H, bool NORM>
__global__ void gate_k(const float* __restrict__ GI, const float* __restrict__ GH,
                       const float* __restrict__ Hp, float* __restrict__ Out) {
    constexpr int NPB = 128 / H;
    __shared__ float sred[8];
    int tid = threadIdx.x;
    int ln = tid / H, j = tid % H;
    int node = blockIdx.x * NPB + ln;
    if (node >= NN) return;

    size_t g = (size_t)node * 3 * H + j;
    float r  = sigm_f(GI[g] + GH[g]);
    float z  = sigm_f(GI[g + H] + GH[g + H]);
    float nc = tanhf(GI[g + 2 * H] + r * GH[g + 2 * H]);
    float hp = Hp[(size_t)node * H + j];
    float h  = (1.f - z) * nc + z * hp;

    if constexpr (NORM) {
        float sq = h * h;
        #pragma unroll
        for (int o = 16; o > 0; o >>= 1) sq += __shfl_xor_sync(0xffffffffu, sq, o);
        int warp = tid >> 5;
        if ((tid & 31) == 0) sred[warp] = sq;
        __syncthreads();
        float tot = sred[ln * 2] + sred[ln * 2 + 1];
        h *= rsqrtf(tot);
    }
    Out[(size_t)node * H + j] = h;
}

// ---------------- launcher ---------------------------------------------------
extern "C" void kernel_launch(void* const* d_in, const int* in_sizes, int n_in,
                              void* d_out, int out_size) {
    const float* x     = (const float*)d_in[0];
    const float* prev0 = (const float*)d_in[1];
    const float* prev1 = (const float*)d_in[2];
    const float* W_p1  = (const float*)d_in[3];
    const float* b_p1  = (const float*)d_in[4];
    const float* W_p2  = (const float*)d_in[5];
    const float* b_p2  = (const float*)d_in[6];
    const float* W_c1  = (const float*)d_in[7];
    const float* b_c1  = (const float*)d_in[8];
    const float* W_c2  = (const float*)d_in[9];
    const float* b_c2  = (const float*)d_in[10];
    const float* Wih1  = (const float*)d_in[11];
    const float* Whh1  = (const float*)d_in[12];
    const float* bih1  = (const float*)d_in[13];
    const float* bhh1  = (const float*)d_in[14];
    const float* Wih2  = (const float*)d_in[15];
    const float* Whh2  = (const float*)d_in[16];
    const float* bih2  = (const float*)d_in[17];
    const float* bhh2  = (const float*)d_in[18];
    const int*   src   = (const int*)d_in[19];
    const int*   dst   = (const int*)d_in[20];

    float* out  = (float*)d_out;
    float* emb0 = out + (size_t)NN * 32;   // output tuple (h[N,32], emb0[N,64]) flattened

    float *H0, *H1, *HW1, *C1, *GI1, *GH1, *HW2, *C2, *GI2, *GH2, *dinv;
    int *deg, *off, *cur, *csr, *bsum;
    cudaGetSymbolAddress((void**)&H0,   g_H0);
    cudaGetSymbolAddress((void**)&H1,   g_H1);
    cudaGetSymbolAddress((void**)&HW1,  g_HW1);
    cudaGetSymbolAddress((void**)&C1,   g_C1);
    cudaGetSymbolAddress((void**)&GI1,  g_GI1);
    cudaGetSymbolAddress((void**)&GH1,  g_GH1);
    cudaGetSymbolAddress((void**)&HW2,  g_HW2);
    cudaGetSymbolAddress((void**)&C2,   g_C2);
    cudaGetSymbolAddress((void**)&GI2,  g_GI2);
    cudaGetSymbolAddress((void**)&GH2,  g_GH2);
    cudaGetSymbolAddress((void**)&dinv, g_dinv);
    cudaGetSymbolAddress((void**)&deg,  g_deg);
    cudaGetSymbolAddress((void**)&off,  g_off);
    cudaGetSymbolAddress((void**)&cur,  g_cur);
    cudaGetSymbolAddress((void**)&csr,  g_csr);
    cudaGetSymbolAddress((void**)&bsum, g_bsum);

    const int MB = (NN + 127) / 128;   // 782 row-blocks
    const int NB = (NN + 255) / 256;   // 391 scan blocks

    // degrees -> dinv, CSR build (reused by both conv layers)
    zero_deg_k<<<(NN + 255) / 256, 256>>>(deg);
    deg_k<<<(NE + 255) / 256, 256>>>(dst, deg);
    dinv_k<<<(NN + 255) / 256, 256>>>(deg, dinv);
    scan_part_k<<<NB, 256>>>(deg, bsum);
    scan_top_k<<<1, 512>>>(bsum, NB);
    scan_final_k<<<NB, 256>>>(deg, bsum, off, cur);
    fill_k<<<(NE + 255) / 256, 256>>>(src, dst, cur, csr);

    // preprocess MLP (bf16x3 tensor-core)
    { dim3 g(2, MB); bf16gemm_k<<<g, 256>>>(x,  W_p1, b_p1, H0, NN, 256, 256); }
    { dim3 g(1, MB); bf16gemm_k<<<g, 256>>>(H0, W_p2, b_p2, H1, NN, 128, 256); }

    // conv1: hw*dinv (HW1), then CSR gather (fused self-loop + bias + leaky)
    { dim3 g(1, MB); bf16gemm64_k<2><<<g, 256>>>(H1, W_c1, nullptr, dinv, HW1, NN, 64, 128); }
    gather_k<64><<<(NN + 3) / 4, 256>>>(off, deg, csr, HW1, dinv, b_c1, C1);

    // GRU1 gates + gating + L2 normalize -> emb0 (second output, also conv2 input)
    { dim3 g(3, MB); bf16gemm64_k<1><<<g, 256>>>(C1,    Wih1, bih1, nullptr, GI1, NN, 192, 64); }
    { dim3 g(3, MB); bf16gemm64_k<1><<<g, 256>>>(prev0, Whh1, bhh1, nullptr, GH1, NN, 192, 64); }
    gate_k<64, true><<<NN / 2, 128>>>(GI1, GH1, prev0, emb0);

    // conv2
    { dim3 g(1, MB); bf16gemm64_k<2><<<g, 256>>>(emb0, W_c2, nullptr, dinv, HW2, NN, 32, 64); }
    gather_k<32><<<(NN + 7) / 8, 256>>>(off, deg, csr, HW2, dinv, b_c2, C2);

    // GRU2 gates + gating -> h (first output)
    { dim3 g(2, MB); bf16gemm64_k<1><<<g, 256>>>(C2,    Wih2, bih2, nullptr, GI2, NN, 96, 32); }
    { dim3 g(2, MB); bf16gemm64_k<1><<<g, 256>>>(prev1, Whh2, bhh2, nullptr, GH2, NN, 96, 32); }
    gate_k<32, false><<<NN / 4, 128>>>(GI2, GH2, prev1, out);
}

// round 7
// speedup vs baseline: 2.1587x; 1.0003x over previous
#include <cuda_runtime.h>
#include <cuda_bf16.h>
#include <math.h>
#include <stdint.h>

#define NN 100000
#define NE 1600000

// ---------------- scratch (static device globals; no runtime allocation) ----
__device__ float g_H0  [(size_t)NN*256];
__device__ float g_H1  [(size_t)NN*128];
__device__ float g_HW1 [(size_t)NN*64];
__device__ float g_C1  [(size_t)NN*64];
__device__ float g_GI1 [(size_t)NN*192];
__device__ float g_GH1 [(size_t)NN*192];
__device__ float g_HW2 [(size_t)NN*32];
__device__ float g_C2  [(size_t)NN*32];
__device__ float g_GI2 [(size_t)NN*96];
__device__ float g_GH2 [(size_t)NN*96];
__device__ float g_dinv[NN];
__device__ int   g_deg [NN];
__device__ int   g_off [NN];
__device__ int   g_cur [NN];
__device__ int   g_csr [NE];
__device__ int   g_bsum[512];

__device__ __forceinline__ float leaky_f(float v) { return v > 0.f ? v : 0.01f * v; }
__device__ __forceinline__ float sigm_f(float x)  { return 1.f / (1.f + expf(-x)); }

// pack two f32 -> bf16x2; 'e' (even-k) goes to the LOW half, 'o' to the HIGH half
__device__ __forceinline__ uint32_t packbf(float e, float o) {
    uint32_t r;
    asm("cvt.rn.bf16x2.f32 %0, %1, %2;" : "=r"(r) : "f"(o), "f"(e));
    return r;
}
__device__ __forceinline__ float bf_hi(float a) {
    return __bfloat162float(__float2bfloat16(a));
}
__device__ __forceinline__ void mma_bf16(float c[4], const uint32_t a[4],
                                         uint32_t b0, uint32_t b1) {
    asm("mma.sync.aligned.m16n8k16.row.col.f32.bf16.bf16.f32 "
        "{%0,%1,%2,%3},{%4,%5,%6,%7},{%8,%9},{%0,%1,%2,%3};"
        : "+f"(c[0]), "+f"(c[1]), "+f"(c[2]), "+f"(c[3])
        : "r"(a[0]), "r"(a[1]), "r"(a[2]), "r"(a[3]), "r"(b0), "r"(b1));
}

// ---------------- BF16x3 tensor-core GEMM, BN=128 ----------------------------
// C[M,N] = leaky(A[M,K] @ B[K,N] + bias[col]).  BM=128, BN=128, BK=16.
// 256 threads = 8 warps (4xM, 2xN); warp tile 32x64. K multiple of 16.
// Packed layout: X2[row][kk] = bf16x2 of k=2kk (low) and k=2kk+1 (high).
__global__ void __launch_bounds__(256, 2)
bf16gemm_k(const float* __restrict__ A, const float* __restrict__ B,
           const float* __restrict__ bias, float* __restrict__ C,
           int M, int N, int K) {
    __shared__ uint32_t A2h[128][12], A2l[128][12];   // cols 0..7 used; stride 12 conflict-free
    __shared__ uint32_t B2h[8][136],  B2l[8][136];    // cols 0..127 used; 136 mod 32 == 8

    const int t    = threadIdx.x;
    const int lane = t & 31, wid = t >> 5;
    const int g    = lane >> 2, tg = lane & 3;
    const int wm   = (wid & 3) * 32;
    const int wn   = (wid >> 2) * 64;
    const int bx = blockIdx.x, by = blockIdx.y;

    float acc[2][8][4];
    #pragma unroll
    for (int i = 0; i < 2; i++)
        #pragma unroll
        for (int j = 0; j < 8; j++)
            #pragma unroll
            for (int q = 0; q < 4; q++) acc[i][j][q] = 0.f;

    for (int k0 = 0; k0 < K; k0 += 16) {
        __syncthreads();
        // stage A (128x16): 512 float4 units, 2 per thread
        #pragma unroll
        for (int p = t; p < 512; p += 256) {
            int row = p >> 2, kc = (p & 3) * 4, kk = (p & 3) * 2;
            int gr = by * 128 + row;
            float4 v = make_float4(0.f, 0.f, 0.f, 0.f);
            if (gr < M) v = *reinterpret_cast<const float4*>(A + (size_t)gr * K + k0 + kc);
            float hx = bf_hi(v.x), hy = bf_hi(v.y), hz = bf_hi(v.z), hw = bf_hi(v.w);
            A2h[row][kk    ] = packbf(v.x, v.y);
            A2h[row][kk + 1] = packbf(v.z, v.w);
            A2l[row][kk    ] = packbf(v.x - hx, v.y - hy);
            A2l[row][kk + 1] = packbf(v.z - hz, v.w - hw);
        }
        // stage B (16x128): 256 (kpair, 4n) units, 1 per thread
        {
            int kk = t >> 5, n4 = (t & 31) * 4;
            const float* bp = B + (size_t)(k0 + 2 * kk) * N + bx * 128 + n4;
            float4 u = *reinterpret_cast<const float4*>(bp);       // k = 2kk
            float4 w = *reinterpret_cast<const float4*>(bp + N);   // k = 2kk+1
            float hux = bf_hi(u.x), huy = bf_hi(u.y), huz = bf_hi(u.z), huw = bf_hi(u.w);
            float hwx = bf_hi(w.x), hwy = bf_hi(w.y), hwz = bf_hi(w.z), hww = bf_hi(w.w);
            B2h[kk][n4 + 0] = packbf(u.x, w.x);
            B2h[kk][n4 + 1] = packbf(u.y, w.y);
            B2h[kk][n4 + 2] = packbf(u.z, w.z);
            B2h[kk][n4 + 3] = packbf(u.w, w.w);
            B2l[kk][n4 + 0] = packbf(u.x - hux, w.x - hwx);
            B2l[kk][n4 + 1] = packbf(u.y - huy, w.y - hwy);
            B2l[kk][n4 + 2] = packbf(u.z - huz, w.z - hwz);
            B2l[kk][n4 + 3] = packbf(u.w - huw, w.w - hww);
        }
        __syncthreads();

        uint32_t ah[2][4], al[2][4];
        #pragma unroll
        for (int i = 0; i < 2; i++) {
            int r0 = wm + i * 16 + g;
            ah[i][0] = A2h[r0    ][tg    ]; ah[i][1] = A2h[r0 + 8][tg    ];
            ah[i][2] = A2h[r0    ][tg + 4]; ah[i][3] = A2h[r0 + 8][tg + 4];
            al[i][0] = A2l[r0    ][tg    ]; al[i][1] = A2l[r0 + 8][tg    ];
            al[i][2] = A2l[r0    ][tg + 4]; al[i][3] = A2l[r0 + 8][tg + 4];
        }
        #pragma unroll
        for (int j = 0; j < 8; j++) {
            int cb = wn + j * 8 + g;
            uint32_t bh0 = B2h[tg][cb], bh1 = B2h[tg + 4][cb];
            uint32_t bl0 = B2l[tg][cb], bl1 = B2l[tg + 4][cb];
            #pragma unroll
            for (int i = 0; i < 2; i++) {
                mma_bf16(acc[i][j], ah[i], bh0, bh1);   // hi*hi
                mma_bf16(acc[i][j], al[i], bh0, bh1);   // lo*hi
                mma_bf16(acc[i][j], ah[i], bl0, bl1);   // hi*lo
            }
        }
    }

    #pragma unroll
    for (int i = 0; i < 2; i++) {
        int gr0 = by * 128 + wm + i * 16 + g;
        #pragma unroll
        for (int j = 0; j < 8; j++) {
            int gc = bx * 128 + wn + j * 8 + 2 * tg;
            float b0 = bias[gc], b1 = bias[gc + 1];
            if (gr0 < M) {
                float2 v = make_float2(leaky_f(acc[i][j][0] + b0),
                                       leaky_f(acc[i][j][1] + b1));
                *reinterpret_cast<float2*>(C + (size_t)gr0 * N + gc) = v;
            }
            if (gr0 + 8 < M) {
                float2 v = make_float2(leaky_f(acc[i][j][2] + b0),
                                       leaky_f(acc[i][j][3] + b1));
                *reinterpret_cast<float2*>(C + (size_t)(gr0 + 8) * N + gc) = v;
            }
        }
    }
}

// ---------------- BF16x3 tensor-core GEMM, BN=64 (small-N layers) ------------
// MODE 1: C = acc + bias[col];  MODE 2: C = acc * dinv[row]
template<int MODE>
__global__ void __launch_bounds__(256, 2)
bf16gemm64_k(const float* __restrict__ A, const float* __restrict__ B,
             const float* __restrict__ bias, const float* __restrict__ dinv,
             float* __restrict__ C, int M, int N, int K) {
    __shared__ uint32_t A2h[128][12], A2l[128][12];
    __shared__ uint32_t B2h[8][72],  B2l[8][72];      // 72 mod 32 == 8: conflict-free

    const int t    = threadIdx.x;
    const int lane = t & 31, wid = t >> 5;
    const int g    = lane >> 2, tg = lane & 3;
    const int wm   = (wid & 3) * 32;
    const int wn   = (wid >> 2) * 32;
    const int bx = blockIdx.x, by = blockIdx.y;

    float acc[2][4][4];
    #pragma unroll
    for (int i = 0; i < 2; i++)
        #pragma unroll
        for (int j = 0; j < 4; j++)
            #pragma unroll
            for (int q = 0; q < 4; q++) acc[i][j][q] = 0.f;

    for (int k0 = 0; k0 < K; k0 += 16) {
        __syncthreads();
        #pragma unroll
        for (int p = t; p < 512; p += 256) {
            int row = p >> 2, kc = (p & 3) * 4, kk = (p & 3) * 2;
            int gr = by * 128 + row;
            float4 v = make_float4(0.f, 0.f, 0.f, 0.f);
            if (gr < M) v = *reinterpret_cast<const float4*>(A + (size_t)gr * K + k0 + kc);
            float hx = bf_hi(v.x), hy = bf_hi(v.y), hz = bf_hi(v.z), hw = bf_hi(v.w);
            A2h[row][kk    ] = packbf(v.x, v.y);
            A2h[row][kk + 1] = packbf(v.z, v.w);
            A2l[row][kk    ] = packbf(v.x - hx, v.y - hy);
            A2l[row][kk + 1] = packbf(v.z - hz, v.w - hw);
        }
        // stage B (16x64): 128 (kpair, 4n) units on threads t<128; zero-fill cols >= N
        if (t < 128) {
            int kk = t >> 4, n4 = (t & 15) * 4;
            int gc = bx * 64 + n4;
            float4 u = make_float4(0.f, 0.f, 0.f, 0.f);
            float4 w = make_float4(0.f, 0.f, 0.f, 0.f);
            if (gc + 3 < N) {
                const float* bp = B + (size_t)(k0 + 2 * kk) * N + gc;
                u = *reinterpret_cast<const float4*>(bp);
                w = *reinterpret_cast<const float4*>(bp + N);
            }
            float hux = bf_hi(u.x), huy = bf_hi(u.y), huz = bf_hi(u.z), huw = bf_hi(u.w);
            float hwx = bf_hi(w.x), hwy = bf_hi(w.y), hwz = bf_hi(w.z), hww = bf_hi(w.w);
            B2h[kk][n4 + 0] = packbf(u.x, w.x);
            B2h[kk][n4 + 1] = packbf(u.y, w.y);
            B2h[kk][n4 + 2] = packbf(u.z, w.z);
            B2h[kk][n4 + 3] = packbf(u.w, w.w);
            B2l[kk][n4 + 0] = packbf(u.x - hux, w.x - hwx);
            B2l[kk][n4 + 1] = packbf(u.y - huy, w.y - hwy);
            B2l[kk][n4 + 2] = packbf(u.z - huz, w.z - hwz);
            B2l[kk][n4 + 3] = packbf(u.w - huw, w.w - hww);
        }
        __syncthreads();

        uint32_t ah[2][4], al[2][4];
        #pragma unroll
        for (int i = 0; i < 2; i++) {
            int r0 = wm + i * 16 + g;
            ah[i][0] = A2h[r0    ][tg    ]; ah[i][1] = A2h[r0 + 8][tg    ];
            ah[i][2] = A2h[r0    ][tg + 4]; ah[i][3] = A2h[r0 + 8][tg + 4];
            al[i][0] = A2l[r0    ][tg    ]; al[i][1] = A2l[r0 + 8][tg    ];
            al[i][2] = A2l[r0    ][tg + 4]; al[i][3] = A2l[r0 + 8][tg + 4];
        }
        #pragma unroll
        for (int j = 0; j < 4; j++) {
            int cb = wn + j * 8 + g;
            uint32_t bh0 = B2h[tg][cb], bh1 = B2h[tg + 4][cb];
            uint32_t bl0 = B2l[tg][cb], bl1 = B2l[tg + 4][cb];
            #pragma unroll
            for (int i = 0; i < 2; i++) {
                mma_bf16(acc[i][j], ah[i], bh0, bh1);
                mma_bf16(acc[i][j], al[i], bh0, bh1);
                mma_bf16(acc[i][j], ah[i], bl0, bl1);
            }
        }
    }

    #pragma unroll
    for (int i = 0; i < 2; i++) {
        int gr0 = by * 128 + wm + i * 16 + g;
        float d0 = (MODE == 2 && gr0     < M) ? dinv[gr0]     : 0.f;
        float d1 = (MODE == 2 && gr0 + 8 < M) ? dinv[gr0 + 8] : 0.f;
        #pragma unroll
        for (int j = 0; j < 4; j++) {
            int gc = bx * 64 + wn + j * 8 + 2 * tg;
            if (gc >= N) continue;
            float b0 = 0.f, b1 = 0.f;
            if (MODE == 1) { b0 = bias[gc]; b1 = bias[gc + 1]; }
            if (gr0 < M) {
                float v0 = (MODE == 1) ? acc[i][j][0] + b0 : acc[i][j][0] * d0;
                float v1 = (MODE == 1) ? acc[i][j][1] + b1 : acc[i][j][1] * d0;
                *reinterpret_cast<float2*>(C + (size_t)gr0 * N + gc) = make_float2(v0, v1);
            }
            if (gr0 + 8 < M) {
                float v0 = (MODE == 1) ? acc[i][j][2] + b0 : acc[i][j][2] * d1;
                float v1 = (MODE == 1) ? acc[i][j][3] + b1 : acc[i][j][3] * d1;
                *reinterpret_cast<float2*>(C + (size_t)(gr0 + 8) * N + gc) = make_float2(v0, v1);
            }
        }
    }
}

// ---------------- degree / dinv ---------------------------------------------
__global__ void zero_deg_k(int* deg) {
    int i = blockIdx.x * blockDim.x + threadIdx.x;
    if (i < NN) deg[i] = 0;
}
__global__ void deg_k(const int* __restrict__ dst, int* __restrict__ deg) {
    int e = blockIdx.x * blockDim.x + threadIdx.x;
    if (e < NE) atomicAdd(&deg[dst[e]], 1);
}
__global__ void dinv_k(const int* __restrict__ deg, float* __restrict__ dinv) {
    int i = blockIdx.x * blockDim.x + threadIdx.x;
    if (i < NN) dinv[i] = rsqrtf((float)deg[i] + 1.0f);
}

// ---------------- parallel CSR prefix sum (3 kernels) ------------------------
__global__ void scan_part_k(const int* __restrict__ deg, int* __restrict__ bsum) {
    __shared__ int s[256];
    int t = threadIdx.x;
    int i = blockIdx.x * 256 + t;
    s[t] = (i < NN) ? deg[i] : 0;
    __syncthreads();
    for (int o = 128; o > 0; o >>= 1) {
        if (t < o) s[t] += s[t + o];
        __syncthreads();
    }
    if (t == 0) bsum[blockIdx.x] = s[0];
}
__global__ void scan_top_k(int* __restrict__ bsum, int nb) {
    __shared__ int s[512];
    int t = threadIdx.x;
    int v = (t < nb) ? bsum[t] : 0;
    s[t] = v;
    __syncthreads();
    for (int o = 1; o < 512; o <<= 1) {
        int u = (t >= o) ? s[t - o] : 0;
        __syncthreads();
        s[t] += u;
        __syncthreads();
    }
    if (t < nb) bsum[t] = s[t] - v;   // exclusive
}
__global__ void scan_final_k(const int* __restrict__ deg, const int* __restrict__ bsum,
                             int* __restrict__ off, int* __restrict__ cur) {
    __shared__ int s[256];
    int t = threadIdx.x;
    int i = blockIdx.x * 256 + t;
    int d = (i < NN) ? deg[i] : 0;
    s[t] = d;
    __syncthreads();
    for (int o = 1; o < 256; o <<= 1) {
        int u = (t >= o) ? s[t - o] : 0;
        __syncthreads();
        s[t] += u;
        __syncthreads();
    }
    if (i < NN) {
        int o_ = bsum[blockIdx.x] + s[t] - d;
        off[i] = o_;
        cur[i] = o_;
    }
}

__global__ void fill_k(const int* __restrict__ src, const int* __restrict__ dst,
                       int* __restrict__ cur, int* __restrict__ csr) {
    int e = blockIdx.x * blockDim.x + threadIdx.x;
    if (e < NE) {
        int pos = atomicAdd(&cur[dst[e]], 1);
        csr[pos] = src[e];
    }
}

// ---------------- CSR gather: fused conv agg + self-loop + bias + leaky -----
template<int F>
__global__ void gather_k(const int* __restrict__ off, const int* __restrict__ deg,
                         const int* __restrict__ csr, const float* __restrict__ HWd,
                         const float* __restrict__ dinv, const float* __restrict__ bias,
                         float* __restrict__ Out) {
    constexpr int NPB = 256 / F;
    int tid = threadIdx.x;
    int ln = tid / F, f = tid % F;
    int n = blockIdx.x * NPB + ln;
    if (n >= NN) return;

    int s0 = off[n], cnt = deg[n];
    float a0 = 0.f, a1 = 0.f, a2 = 0.f, a3 = 0.f;
    int i = 0;
    for (; i + 4 <= cnt; i += 4) {
        int e0 = csr[s0 + i], e1 = csr[s0 + i + 1];
        int e2 = csr[s0 + i + 2], e3 = csr[s0 + i + 3];
        a0 += HWd[(size_t)e0 * F + f];
        a1 += HWd[(size_t)e1 * F + f];
        a2 += HWd[(size_t)e2 * F + f];
        a3 += HWd[(size_t)e3 * F + f];
    }
    for (; i < cnt; i++) a0 += HWd[(size_t)csr[s0 + i] * F + f];

    float sum = (a0 + a1) + (a2 + a3);
    float v = dinv[n] * (sum + HWd[(size_t)n * F + f]) + bias[f];
    Out[(size_t)n * F + f] = leaky_f(v);
}

// ---------------- GRU gating (+ optional row L2 normalize) ------------------
template<int H, bool NORM>
__global__ void gate_k(const float* __restrict__ GI, const float* __restrict__ GH,
                       const float* __restrict__ Hp, float* __restrict__ Out) {
    constexpr int NPB = 128 / H;
    __shared__ float sred[8];
    int tid = threadIdx.x;
    int ln = tid / H, j = tid % H;
    int node = blockIdx.x * NPB + ln;
    if (node >= NN) return;

    size_t g = (size_t)node * 3 * H + j;
    float r  = sigm_f(GI[g] + GH[g]);
    float z  = sigm_f(GI[g + H] + GH[g + H]);
    float nc = tanhf(GI[g + 2 * H] + r * GH[g + 2 * H]);
    float hp = Hp[(size_t)node * H + j];
    float h  = (1.f - z) * nc + z * hp;

    if constexpr (NORM) {
        float sq = h * h;
        #pragma unroll
        for (int o = 16; o > 0; o >>= 1) sq += __shfl_xor_sync(0xffffffffu, sq, o);
        int warp = tid >> 5;
        if ((tid & 31) == 0) sred[warp] = sq;
        __syncthreads();
        float tot = sred[ln * 2] + sred[ln * 2 + 1];
        h *= rsqrtf(tot);
    }
    Out[(size_t)node * H + j] = h;
}

// ---------------- launcher ---------------------------------------------------
extern "C" void kernel_launch(void* const* d_in, const int* in_sizes, int n_in,
                              void* d_out, int out_size) {
    const float* x     = (const float*)d_in[0];
    const float* prev0 = (const float*)d_in[1];
    const float* prev1 = (const float*)d_in[2];
    const float* W_p1  = (const float*)d_in[3];
    const float* b_p1  = (const float*)d_in[4];
    const float* W_p2  = (const float*)d_in[5];
    const float* b_p2  = (const float*)d_in[6];
    const float* W_c1  = (const float*)d_in[7];
    const float* b_c1  = (const float*)d_in[8];
    const float* W_c2  = (const float*)d_in[9];
    const float* b_c2  = (const float*)d_in[10];
    const float* Wih1  = (const float*)d_in[11];
    const float* Whh1  = (const float*)d_in[12];
    const float* bih1  = (const float*)d_in[13];
    const float* bhh1  = (const float*)d_in[14];
    const float* Wih2  = (const float*)d_in[15];
    const float* Whh2  = (const float*)d_in[16];
    const float* bih2  = (const float*)d_in[17];
    const float* bhh2  = (const float*)d_in[18];
    const int*   src   = (const int*)d_in[19];
    const int*   dst   = (const int*)d_in[20];

    float* out  = (float*)d_out;
    float* emb0 = out + (size_t)NN * 32;   // output tuple (h[N,32], emb0[N,64]) flattened

    float *H0, *H1, *HW1, *C1, *GI1, *GH1, *HW2, *C2, *GI2, *GH2, *dinv;
    int *deg, *off, *cur, *csr, *bsum;
    cudaGetSymbolAddress((void**)&H0,   g_H0);
    cudaGetSymbolAddress((void**)&H1,   g_H1);
    cudaGetSymbolAddress((void**)&HW1,  g_HW1);
    cudaGetSymbolAddress((void**)&C1,   g_C1);
    cudaGetSymbolAddress((void**)&GI1,  g_GI1);
    cudaGetSymbolAddress((void**)&GH1,  g_GH1);
    cudaGetSymbolAddress((void**)&HW2,  g_HW2);
    cudaGetSymbolAddress((void**)&C2,   g_C2);
    cudaGetSymbolAddress((void**)&GI2,  g_GI2);
    cudaGetSymbolAddress((void**)&GH2,  g_GH2);
    cudaGetSymbolAddress((void**)&dinv, g_dinv);
    cudaGetSymbolAddress((void**)&deg,  g_deg);
    cudaGetSymbolAddress((void**)&off,  g_off);
    cudaGetSymbolAddress((void**)&cur,  g_cur);
    cudaGetSymbolAddress((void**)&csr,  g_csr);
    cudaGetSymbolAddress((void**)&bsum, g_bsum);

    const int MB = (NN + 127) / 128;   // 782 row-blocks
    const int NB = (NN + 255) / 256;   // 391 scan blocks

    // degrees -> dinv, CSR build (reused by both conv layers)
    zero_deg_k<<<(NN + 255) / 256, 256>>>(deg);
    deg_k<<<(NE + 255) / 256, 256>>>(dst, deg);
    dinv_k<<<(NN + 255) / 256, 256>>>(deg, dinv);
    scan_part_k<<<NB, 256>>>(deg, bsum);
    scan_top_k<<<1, 512>>>(bsum, NB);
    scan_final_k<<<NB, 256>>>(deg, bsum, off, cur);
    fill_k<<<(NE + 255) / 256, 256>>>(src, dst, cur, csr);

    // preprocess MLP (bf16x3 tensor-core)
    { dim3 g(2, MB); bf16gemm_k<<<g, 256>>>(x,  W_p1, b_p1, H0, NN, 256, 256); }
    { dim3 g(1, MB); bf16gemm_k<<<g, 256>>>(H0, W_p2, b_p2, H1, NN, 128, 256); }

    // conv1: hw*dinv (HW1), then CSR gather (fused self-loop + bias + leaky)
    { dim3 g(1, MB); bf16gemm64_k<2><<<g, 256>>>(H1, W_c1, nullptr, dinv, HW1, NN, 64, 128); }
    gather_k<64><<<(NN + 3) / 4, 256>>>(off, deg, csr, HW1, dinv, b_c1, C1);

    // GRU1 gates + gating + L2 normalize -> emb0 (second output, also conv2 input)
    { dim3 g(3, MB); bf16gemm64_k<1><<<g, 256>>>(C1,    Wih1, bih1, nullptr, GI1, NN, 192, 64); }
    { dim3 g(3, MB); bf16gemm64_k<1><<<g, 256>>>(prev0, Whh1, bhh1, nullptr, GH1, NN, 192, 64); }
    gate_k<64, true><<<NN / 2, 128>>>(GI1, GH1, prev0, emb0);

    // conv2
    { dim3 g(1, MB); bf16gemm64_k<2><<<g, 256>>>(emb0, W_c2, nullptr, dinv, HW2, NN, 32, 64); }
    gather_k<32><<<(NN + 7) / 8, 256>>>(off, deg, csr, HW2, dinv, b_c2, C2);

    // GRU2 gates + gating -> h (first output)
    { dim3 g(2, MB); bf16gemm64_k<1><<<g, 256>>>(C2,    Wih2, bih2, nullptr, GI2, NN, 96, 32); }
    { dim3 g(2, MB); bf16gemm64_k<1><<<g, 256>>>(prev1, Whh2, bhh2, nullptr, GH2, NN, 96, 32); }
    gate_k<32, false><<<NN / 4, 128>>>(GI2, GH2, prev1, out);
}